// round 3
// baseline (speedup 1.0000x reference)
#include <cuda_runtime.h>

typedef unsigned long long u64;
typedef long long ll;

// ---------------- scratch (no allocations allowed) ----------------
__device__ float g_gi_f[64 * 1024 * 384];
__device__ float g_gi_b[64 * 1024 * 384];
__device__ float g_z0[64 * 1024 * 256];
__device__ float g_z1[64 * 1024 * 256];

// ---------------- f32x2 helpers ----------------
__device__ __forceinline__ u64 ffma2(u64 a, u64 b, u64 c) {
    u64 d;
    asm("fma.rn.f32x2 %0, %1, %2, %3;" : "=l"(d) : "l"(a), "l"(b), "l"(c));
    return d;
}
__device__ __forceinline__ u64 addf2(u64 a, u64 b) {
    u64 d;
    asm("add.rn.f32x2 %0, %1, %2;" : "=l"(d) : "l"(a), "l"(b));
    return d;
}
__device__ __forceinline__ u64 pack2(float lo, float hi) {
    u64 r;
    asm("mov.b64 %0, {%1, %2};" : "=l"(r) : "f"(lo), "f"(hi));
    return r;
}
__device__ __forceinline__ float2 unpack2(u64 v) {
    float2 f;
    asm("mov.b64 {%0, %1}, %2;" : "=f"(f.x), "=f"(f.y) : "l"(v));
    return f;
}

__device__ __forceinline__ float tanh_mufu(float x) {
    float y;
    asm("tanh.approx.f32 %0, %1;" : "=f"(y) : "f"(x));
    return y;
}
__device__ __forceinline__ float sig_mufu(float x) {
    return fmaf(0.5f, tanh_mufu(0.5f * x), 0.5f);
}
__device__ __forceinline__ float sigmoid_exact(float x) {
    return __fdividef(1.0f, 1.0f + __expf(-x));
}

// ---------------- GEMM: C[M,384] = A[M,K] @ W[384,K]^T + bias ----------------
// BM=128, BN=128, BK=16, 256 threads, 8x8 per thread via f32x2 (n-pairs packed).
// A stored in smem as duplicated (a,a) u64 pairs -> no per-k MOV duplication.
// W transposed in smem so n-pairs load as native u64.
__global__ __launch_bounds__(256, 2) void gemm2(
    const float* __restrict__ A,
    const float* __restrict__ Wf, const float* __restrict__ Wb,
    const float* __restrict__ bf, const float* __restrict__ bb,
    float* __restrict__ Cf, float* __restrict__ Cb,
    int K)
{
    const int N = 384;
    const float* W    = blockIdx.z ? Wb : Wf;
    const float* bias = blockIdx.z ? bb : bf;
    float*       C    = blockIdx.z ? Cb : Cf;

    const int mBase = blockIdx.y * 128;
    const int nBase = blockIdx.x * 128;
    const int tid = threadIdx.x;
    const int tx = tid & 15;        // n octet
    const int ty = tid >> 4;        // m octet
    const int m0 = ty * 8;          // u64 index into Asd row
    const int n0 = tx * 8;          // float index into Wt row

    __shared__ __align__(16) u64   Asd[16][130];  // duplicated (a,a) pairs [k][m]
    __shared__ __align__(16) float Wt[16][132];   // transposed W tile [k][n]

    u64 acc[8][4];
#pragma unroll
    for (int mi = 0; mi < 8; mi++)
#pragma unroll
        for (int nj = 0; nj < 4; nj++) acc[mi][nj] = 0ULL;

    const int la_m = tid >> 1;          // 0..127
    const int la_k = (tid & 1) * 8;     // 0 or 8

    const float* Ap = A + (ll)(mBase + la_m) * K + la_k;
    const float* Wp = W + (ll)(nBase + la_m) * K + la_k;

    for (int k0 = 0; k0 < K; k0 += 16) {
        float4 a0 = *(const float4*)(Ap + k0);
        float4 a1 = *(const float4*)(Ap + k0 + 4);
        float4 w0 = *(const float4*)(Wp + k0);
        float4 w1 = *(const float4*)(Wp + k0 + 4);
        __syncthreads();
        Asd[la_k + 0][la_m] = pack2(a0.x, a0.x);
        Asd[la_k + 1][la_m] = pack2(a0.y, a0.y);
        Asd[la_k + 2][la_m] = pack2(a0.z, a0.z);
        Asd[la_k + 3][la_m] = pack2(a0.w, a0.w);
        Asd[la_k + 4][la_m] = pack2(a1.x, a1.x);
        Asd[la_k + 5][la_m] = pack2(a1.y, a1.y);
        Asd[la_k + 6][la_m] = pack2(a1.z, a1.z);
        Asd[la_k + 7][la_m] = pack2(a1.w, a1.w);
        Wt[la_k + 0][la_m] = w0.x;
        Wt[la_k + 1][la_m] = w0.y;
        Wt[la_k + 2][la_m] = w0.z;
        Wt[la_k + 3][la_m] = w0.w;
        Wt[la_k + 4][la_m] = w1.x;
        Wt[la_k + 5][la_m] = w1.y;
        Wt[la_k + 6][la_m] = w1.z;
        Wt[la_k + 7][la_m] = w1.w;
        __syncthreads();
#pragma unroll
        for (int k = 0; k < 16; k++) {
            const ulonglong2* ap = (const ulonglong2*)&Asd[k][m0];
            ulonglong2 A01 = ap[0];
            ulonglong2 A23 = ap[1];
            ulonglong2 A45 = ap[2];
            ulonglong2 A67 = ap[3];
            u64 am[8] = { A01.x, A01.y, A23.x, A23.y,
                          A45.x, A45.y, A67.x, A67.y };
            ulonglong2 b01 = *(const ulonglong2*)&Wt[k][n0];
            ulonglong2 b23 = *(const ulonglong2*)&Wt[k][n0 + 4];
            u64 bn[4] = { b01.x, b01.y, b23.x, b23.y };
#pragma unroll
            for (int mi = 0; mi < 8; mi++)
#pragma unroll
                for (int nj = 0; nj < 4; nj++)
                    acc[mi][nj] = ffma2(am[mi], bn[nj], acc[mi][nj]);
        }
    }

    ulonglong2 bv01 = *(const ulonglong2*)(bias + nBase + n0);
    ulonglong2 bv23 = *(const ulonglong2*)(bias + nBase + n0 + 4);
#pragma unroll
    for (int mi = 0; mi < 8; mi++) {
        float* row = C + (ll)(mBase + m0 + mi) * N + nBase + n0;
        ulonglong2 v0, v1;
        v0.x = addf2(acc[mi][0], bv01.x);
        v0.y = addf2(acc[mi][1], bv01.y);
        v1.x = addf2(acc[mi][2], bv23.x);
        v1.y = addf2(acc[mi][3], bv23.y);
        *(ulonglong2*)(row)     = v0;
        *(ulonglong2*)(row + 4) = v1;
    }
}

// ---------------- GRU scan: 128 CTAs = 64 batch x 2 dirs; Whh in registers ----------------
// gi prefetch pipelined 3 steps deep to hide DRAM latency off the recurrence.
__global__ __launch_bounds__(384, 1) void gru_scan(
    const float* __restrict__ gif, const float* __restrict__ gib,
    const float* __restrict__ whf, const float* __restrict__ bhf,
    const float* __restrict__ whb, const float* __restrict__ bhb,
    float* __restrict__ zout /* [64][1024][256] */)
{
    const int b   = blockIdx.x & 63;
    const int dir = blockIdx.x >> 6;
    const float* gi  = dir ? gib : gif;
    const float* whh = dir ? whb : whf;
    const float* bhh = dir ? bhb : bhf;
    const int j = threadIdx.x;   // rows: [0,128)=r, [128,256)=z, [256,384)=n

    u64 w[64];
    {
        const u64* wp = (const u64*)(whh + j * 128);
#pragma unroll
        for (int k = 0; k < 64; k++) w[k] = wp[k];
    }
    const float bh = bhh[j];

    __shared__ __align__(16) float hsm[128];
    __shared__ float rsm[128];
    __shared__ float zsm[128];
    if (j < 128) hsm[j] = 0.0f;
    __syncthreads();

    const int step = dir ? -1 : 1;
    int tt = dir ? 1023 : 0;
    const float* gip = gi + (ll)b * 1024 * 384 + j;
    float* zrow = zout + (ll)b * 1024 * 256 + dir * 128;

    // 3-deep rolling prefetch window (wrap-indexed; overrun values unused)
    float g0 = gip[(ll)tt * 384];
    float g1 = gip[(ll)((tt + step) & 1023) * 384];
    float g2 = gip[(ll)((tt + 2 * step) & 1023) * 384];

    for (int t = 0; t < 1024; t++) {
        float g3 = gip[(ll)((tt + 3 * step) & 1023) * 384];
        float gcur = g0;

        // gh_j = Whh[j,:] . h  (64 FFMA2 in 4 chains; h broadcast via LDS.128)
        u64 a0 = 0ULL, a1 = 0ULL, a2 = 0ULL, a3 = 0ULL;
        const ulonglong2* hp2 = (const ulonglong2*)hsm;
#pragma unroll
        for (int q = 0; q < 16; q++) {
            ulonglong2 u0 = hp2[2 * q];
            ulonglong2 u1 = hp2[2 * q + 1];
            a0 = ffma2(w[4 * q + 0], u0.x, a0);
            a1 = ffma2(w[4 * q + 1], u0.y, a1);
            a2 = ffma2(w[4 * q + 2], u1.x, a2);
            a3 = ffma2(w[4 * q + 3], u1.y, a3);
        }
        float2 f0 = unpack2(a0), f1 = unpack2(a1);
        float2 f2 = unpack2(a2), f3 = unpack2(a3);
        float gh = ((f0.x + f0.y) + (f1.x + f1.y)) +
                   ((f2.x + f2.y) + (f3.x + f3.y)) + bh;

        float hold = 0.0f;
        if (j >= 256) hold = hsm[j - 256];          // preload before barrier
        if (j < 128) {
            rsm[j] = sig_mufu(gcur + gh);           // r gate (fast MUFU)
        } else if (j < 256) {
            zsm[j - 128] = sigmoid_exact(gcur + gh); // z gate (accurate)
        }
        __syncthreads();
        if (j >= 256) {
            int i = j - 256;
            float n = tanh_mufu(fmaf(rsm[i], gh, gcur));
            float hnew = fmaf(zsm[i], hold - n, n);  // (1-z)n + z h
            hsm[i] = hnew;
            zrow[(ll)tt * 256 + i] = hnew;
        }
        __syncthreads();
        g0 = g1; g1 = g2; g2 = g3;
        tt += step;
    }
}

// ---------------- attention pooling + heads ----------------
__global__ __launch_bounds__(256) void pool_heads(
    const float* __restrict__ z1,
    const float* __restrict__ attn_w, const float* __restrict__ attn_b,
    const float* __restrict__ motor_w, const float* __restrict__ motor_b,
    const float* __restrict__ state_w, const float* __restrict__ state_b,
    const int* __restrict__ motor_k,
    float* __restrict__ out)
{
    const int b = blockIdx.x;
    const int tid = threadIdx.x;
    const int lane = tid & 31;
    const int wrp = tid >> 5;

    __shared__ float aw[256];
    __shared__ float sc[1024];
    __shared__ float pl[256];
    __shared__ float red[40];

    aw[tid] = attn_w[tid];
    __syncthreads();

    const float* zb = z1 + (ll)b * 1024 * 256;

    for (int it = 0; it < 128; it++) {
        int t = it * 8 + wrp;
        const float* zr = zb + (ll)t * 256;
        float p = 0.0f;
#pragma unroll
        for (int q = 0; q < 8; q++)
            p = fmaf(zr[lane + 32 * q], aw[lane + 32 * q], p);
#pragma unroll
        for (int o = 16; o; o >>= 1) p += __shfl_down_sync(0xffffffffu, p, o);
        if (lane == 0) sc[t] = p + attn_b[0];
    }
    __syncthreads();

    float mx = -1e30f;
    for (int t = tid; t < 1024; t += 256) mx = fmaxf(mx, sc[t]);
#pragma unroll
    for (int o = 16; o; o >>= 1) mx = fmaxf(mx, __shfl_down_sync(0xffffffffu, mx, o));
    if (lane == 0) red[wrp] = mx;
    __syncthreads();
    if (tid == 0) {
        float m = red[0];
        for (int i = 1; i < 8; i++) m = fmaxf(m, red[i]);
        red[32] = m;
    }
    __syncthreads();
    mx = red[32];
    float s = 0.0f;
    for (int t = tid; t < 1024; t += 256) {
        float e = __expf(sc[t] - mx);
        sc[t] = e;
        s += e;
    }
#pragma unroll
    for (int o = 16; o; o >>= 1) s += __shfl_down_sync(0xffffffffu, s, o);
    if (lane == 0) red[wrp] = s;
    __syncthreads();
    if (tid == 0) {
        float m = 0.0f;
        for (int i = 0; i < 8; i++) m += red[i];
        red[33] = __fdividef(1.0f, m);
    }
    __syncthreads();
    const float inv = red[33];

    // pooled[d] = sum_t a_t z[b,t,d]  (4-way unrolled, independent chains)
    float ac0 = 0.0f, ac1 = 0.0f, ac2 = 0.0f, ac3 = 0.0f;
    for (int t = 0; t < 1024; t += 4) {
        ac0 = fmaf(sc[t + 0], zb[(ll)(t + 0) * 256 + tid], ac0);
        ac1 = fmaf(sc[t + 1], zb[(ll)(t + 1) * 256 + tid], ac1);
        ac2 = fmaf(sc[t + 2], zb[(ll)(t + 2) * 256 + tid], ac2);
        ac3 = fmaf(sc[t + 3], zb[(ll)(t + 3) * 256 + tid], ac3);
    }
    pl[tid] = ((ac0 + ac1) + (ac2 + ac3)) * inv;
    __syncthreads();

    if (wrp < 7) {
        const float* wv;
        float bias2;
        int k = motor_k[b];
        if (wrp < 5) {
            wv = motor_w + wrp * 256;
            bias2 = motor_b[wrp];
        } else {
            int c = wrp - 5;
            wv = state_w + (k * 2 + c) * 256;
            bias2 = state_b[k * 2 + c];
        }
        float p = 0.0f;
#pragma unroll
        for (int q = 0; q < 8; q++)
            p = fmaf(pl[lane + 32 * q], wv[lane + 32 * q], p);
#pragma unroll
        for (int o = 16; o; o >>= 1) p += __shfl_down_sync(0xffffffffu, p, o);
        if (lane == 0) {
            if (wrp < 5) out[b * 5 + wrp] = p + bias2;
            else         out[320 + b * 2 + (wrp - 5)] = p + bias2;
        }
    }
}

// ---------------- launcher ----------------
extern "C" void kernel_launch(void* const* d_in, const int* in_sizes, int n_in,
                              void* d_out, int out_size)
{
    const float* x        = (const float*)d_in[0];
    const int*   motor_k  = (const int*)d_in[1];
    const float* wih_l0f  = (const float*)d_in[2];
    const float* whh_l0f  = (const float*)d_in[3];
    const float* bih_l0f  = (const float*)d_in[4];
    const float* bhh_l0f  = (const float*)d_in[5];
    const float* wih_l0b  = (const float*)d_in[6];
    const float* whh_l0b  = (const float*)d_in[7];
    const float* bih_l0b  = (const float*)d_in[8];
    const float* bhh_l0b  = (const float*)d_in[9];
    const float* wih_l1f  = (const float*)d_in[10];
    const float* whh_l1f  = (const float*)d_in[11];
    const float* bih_l1f  = (const float*)d_in[12];
    const float* bhh_l1f  = (const float*)d_in[13];
    const float* wih_l1b  = (const float*)d_in[14];
    const float* whh_l1b  = (const float*)d_in[15];
    const float* bih_l1b  = (const float*)d_in[16];
    const float* bhh_l1b  = (const float*)d_in[17];
    const float* attn_w   = (const float*)d_in[18];
    const float* attn_b   = (const float*)d_in[19];
    const float* motor_w  = (const float*)d_in[20];
    const float* motor_b  = (const float*)d_in[21];
    const float* state_w  = (const float*)d_in[22];
    const float* state_b  = (const float*)d_in[23];

    float *gif, *gib, *z0, *z1;
    cudaGetSymbolAddress((void**)&gif, g_gi_f);
    cudaGetSymbolAddress((void**)&gib, g_gi_b);
    cudaGetSymbolAddress((void**)&z0, g_z0);
    cudaGetSymbolAddress((void**)&z1, g_z1);

    dim3 gb(3, 512, 2);   // N/128, M/128, dirs

    // layer 0
    gemm2<<<gb, 256>>>(x, wih_l0f, wih_l0b, bih_l0f, bih_l0b, gif, gib, 64);
    gru_scan<<<128, 384>>>(gif, gib, whh_l0f, bhh_l0f, whh_l0b, bhh_l0b, z0);
    // layer 1
    gemm2<<<gb, 256>>>(z0, wih_l1f, wih_l1b, bih_l1f, bih_l1b, gif, gib, 256);
    gru_scan<<<128, 384>>>(gif, gib, whh_l1f, bhh_l1f, whh_l1b, bhh_l1b, z1);
    // pooling + heads
    pool_heads<<<64, 256>>>(z1, attn_w, attn_b, motor_w, motor_b,
                            state_w, state_b, motor_k, (float*)d_out);
}

// round 4
// speedup vs baseline: 1.1389x; 1.1389x over previous
#include <cuda_runtime.h>

typedef unsigned long long u64;
typedef long long ll;

// ---------------- scratch (no allocations allowed) ----------------
__device__ float g_gi_f[64 * 1024 * 384];
__device__ float g_gi_b[64 * 1024 * 384];
__device__ float g_z0[64 * 1024 * 256];
__device__ float g_z1[64 * 1024 * 256];

// ---------------- f32x2 helpers ----------------
__device__ __forceinline__ u64 ffma2(u64 a, u64 b, u64 c) {
    u64 d;
    asm("fma.rn.f32x2 %0, %1, %2, %3;" : "=l"(d) : "l"(a), "l"(b), "l"(c));
    return d;
}
__device__ __forceinline__ u64 addf2(u64 a, u64 b) {
    u64 d;
    asm("add.rn.f32x2 %0, %1, %2;" : "=l"(d) : "l"(a), "l"(b));
    return d;
}
__device__ __forceinline__ u64 pack2(float lo, float hi) {
    u64 r;
    asm("mov.b64 %0, {%1, %2};" : "=l"(r) : "f"(lo), "f"(hi));
    return r;
}
__device__ __forceinline__ float2 unpack2(u64 v) {
    float2 f;
    asm("mov.b64 {%0, %1}, %2;" : "=f"(f.x), "=f"(f.y) : "l"(v));
    return f;
}

__device__ __forceinline__ float tanh_mufu(float x) {
    float y;
    asm("tanh.approx.f32 %0, %1;" : "=f"(y) : "f"(x));
    return y;
}
__device__ __forceinline__ float sig_mufu(float x) {
    return fmaf(0.5f, tanh_mufu(0.5f * x), 0.5f);
}

// ---------------- GEMM: C[M,384] = A[M,K] @ W[384,K]^T + bias ----------------
// (R2-proven version) BM=128, BN=128, BK=16, 256 threads, 8x8 per thread via
// f32x2 n-pairs; A duplicated into (a,a) pairs in registers; W transposed in smem.
__global__ __launch_bounds__(256, 2) void gemm2(
    const float* __restrict__ A,
    const float* __restrict__ Wf, const float* __restrict__ Wb,
    const float* __restrict__ bf, const float* __restrict__ bb,
    float* __restrict__ Cf, float* __restrict__ Cb,
    int K)
{
    const int N = 384;
    const float* W    = blockIdx.z ? Wb : Wf;
    const float* bias = blockIdx.z ? bb : bf;
    float*       C    = blockIdx.z ? Cb : Cf;

    const int mBase = blockIdx.y * 128;
    const int nBase = blockIdx.x * 128;
    const int tid = threadIdx.x;
    const int tx = tid & 15;
    const int ty = tid >> 4;
    const int m0 = ty * 8;
    const int n0 = tx * 8;

    __shared__ float As[16][132];
    __shared__ float Wt[16][132];

    u64 acc[8][4];
#pragma unroll
    for (int mi = 0; mi < 8; mi++)
#pragma unroll
        for (int nj = 0; nj < 4; nj++) acc[mi][nj] = 0ULL;

    const int la_m = tid >> 1;
    const int la_k = (tid & 1) * 8;

    const float* Ap = A + (ll)(mBase + la_m) * K + la_k;
    const float* Wp = W + (ll)(nBase + la_m) * K + la_k;

    for (int k0 = 0; k0 < K; k0 += 16) {
        float4 a0 = *(const float4*)(Ap + k0);
        float4 a1 = *(const float4*)(Ap + k0 + 4);
        float4 w0 = *(const float4*)(Wp + k0);
        float4 w1 = *(const float4*)(Wp + k0 + 4);
        __syncthreads();
        As[la_k + 0][la_m] = a0.x;
        As[la_k + 1][la_m] = a0.y;
        As[la_k + 2][la_m] = a0.z;
        As[la_k + 3][la_m] = a0.w;
        As[la_k + 4][la_m] = a1.x;
        As[la_k + 5][la_m] = a1.y;
        As[la_k + 6][la_m] = a1.z;
        As[la_k + 7][la_m] = a1.w;
        Wt[la_k + 0][la_m] = w0.x;
        Wt[la_k + 1][la_m] = w0.y;
        Wt[la_k + 2][la_m] = w0.z;
        Wt[la_k + 3][la_m] = w0.w;
        Wt[la_k + 4][la_m] = w1.x;
        Wt[la_k + 5][la_m] = w1.y;
        Wt[la_k + 6][la_m] = w1.z;
        Wt[la_k + 7][la_m] = w1.w;
        __syncthreads();
#pragma unroll
        for (int k = 0; k < 16; k++) {
            float4 aL = *(const float4*)&As[k][m0];
            float4 aH = *(const float4*)&As[k][m0 + 4];
            u64 am[8];
            am[0] = pack2(aL.x, aL.x);
            am[1] = pack2(aL.y, aL.y);
            am[2] = pack2(aL.z, aL.z);
            am[3] = pack2(aL.w, aL.w);
            am[4] = pack2(aH.x, aH.x);
            am[5] = pack2(aH.y, aH.y);
            am[6] = pack2(aH.z, aH.z);
            am[7] = pack2(aH.w, aH.w);
            ulonglong2 b01 = *(const ulonglong2*)&Wt[k][n0];
            ulonglong2 b23 = *(const ulonglong2*)&Wt[k][n0 + 4];
            u64 bn[4] = { b01.x, b01.y, b23.x, b23.y };
#pragma unroll
            for (int mi = 0; mi < 8; mi++)
#pragma unroll
                for (int nj = 0; nj < 4; nj++)
                    acc[mi][nj] = ffma2(am[mi], bn[nj], acc[mi][nj]);
        }
    }

    ulonglong2 bv01 = *(const ulonglong2*)(bias + nBase + n0);
    ulonglong2 bv23 = *(const ulonglong2*)(bias + nBase + n0 + 4);
#pragma unroll
    for (int mi = 0; mi < 8; mi++) {
        float* row = C + (ll)(mBase + m0 + mi) * N + nBase + n0;
        ulonglong2 v0, v1;
        v0.x = addf2(acc[mi][0], bv01.x);
        v0.y = addf2(acc[mi][1], bv01.y);
        v1.x = addf2(acc[mi][2], bv23.x);
        v1.y = addf2(acc[mi][3], bv23.y);
        *(ulonglong2*)(row)     = v0;
        *(ulonglong2*)(row + 4) = v1;
    }
}

// ---------------- GRU scan: 128 CTAs = 64 batch x 2 dirs ----------------
// 768 threads: each of the 384 rows is split across a thread PAIR (j, j+384):
// low thread owns k in [0,64), high thread k in [64,128). Half the weight regs
// per thread (32 u64) -> 24 warps resident (6/SMSP) for latency hiding.
// High threads publish partials via smem; 3 barriers per step.
__global__ __launch_bounds__(768, 1) void gru_scan(
    const float* __restrict__ gif, const float* __restrict__ gib,
    const float* __restrict__ whf, const float* __restrict__ bhf,
    const float* __restrict__ whb, const float* __restrict__ bhb,
    float* __restrict__ zout /* [64][1024][256] */)
{
    const int b   = blockIdx.x & 63;
    const int dir = blockIdx.x >> 6;
    const float* gi  = dir ? gib : gif;
    const float* whh = dir ? whb : whf;
    const float* bhh = dir ? bhb : bhf;

    const int tid = threadIdx.x;
    const bool low = (tid < 384);
    const int j = low ? tid : tid - 384;       // row 0..383
    const int kofs = low ? 0 : 64;

    // half-row of Whh: 32 packed f32x2 regs
    u64 w[32];
    {
        const u64* wp = (const u64*)(whh + j * 128 + kofs);
#pragma unroll
        for (int k = 0; k < 32; k++) w[k] = wp[k];
    }
    const float bh = low ? bhh[j] : 0.0f;

    __shared__ __align__(16) float hsm[128];
    __shared__ float psm[384];
    __shared__ float rsm[128];
    __shared__ float zsm[128];
    if (tid < 128) hsm[tid] = 0.0f;
    __syncthreads();

    const int step = dir ? -1 : 1;
    int tt = dir ? 1023 : 0;
    const float* gip = gi + (ll)b * (1024 * 384) + j;
    float* zb = zout + (ll)b * (1024 * 256) + dir * 128;

    // 1-step-ahead prefetch, consumed NEXT iteration (R2-proven pattern)
    float gcur = low ? gip[tt * 384] : 0.0f;

    for (int t = 0; t < 1024; t++) {
        float gnext = 0.0f;
        if (low) gnext = gip[((tt + step) & 1023) * 384];

        // half dot: 32 FFMA2 over h[kofs : kofs+64) (broadcast LDS.128)
        const ulonglong2* hp2 = (const ulonglong2*)hsm + (low ? 0 : 16);
        u64 a0 = 0ULL, a1 = 0ULL;
#pragma unroll
        for (int q = 0; q < 16; q++) {
            ulonglong2 u = hp2[q];
            a0 = ffma2(w[2 * q],     u.x, a0);
            a1 = ffma2(w[2 * q + 1], u.y, a1);
        }
        float2 f = unpack2(addf2(a0, a1));
        float partial = f.x + f.y;

        if (!low) psm[j] = partial;
        const int i = j - 256;
        float hold = 0.0f;
        if (low && j >= 256) hold = hsm[i];    // hsm stable until after B2
        __syncthreads();                       // B1: partials visible

        float ghn = 0.0f;
        if (low) {
            float gh = partial + psm[j] + bh;
            if (j < 128) {
                rsm[j] = sig_mufu(gcur + gh);
            } else if (j < 256) {
                zsm[j - 128] = sig_mufu(gcur + gh);
            } else {
                ghn = gh;
            }
        }
        __syncthreads();                       // B2: gates visible
        if (low && j >= 256) {
            float n = tanh_mufu(fmaf(rsm[i], ghn, gcur));
            float hnew = fmaf(zsm[i], hold - n, n);   // (1-z)n + z h
            hsm[i] = hnew;
            zb[tt * 256 + i] = hnew;
        }
        __syncthreads();                       // B3: hsm ready for next dot
        gcur = gnext;
        tt += step;
    }
}

// ---------------- attention pooling + heads ----------------
__global__ __launch_bounds__(256) void pool_heads(
    const float* __restrict__ z1,
    const float* __restrict__ attn_w, const float* __restrict__ attn_b,
    const float* __restrict__ motor_w, const float* __restrict__ motor_b,
    const float* __restrict__ state_w, const float* __restrict__ state_b,
    const int* __restrict__ motor_k,
    float* __restrict__ out)
{
    const int b = blockIdx.x;
    const int tid = threadIdx.x;
    const int lane = tid & 31;
    const int wrp = tid >> 5;

    __shared__ float aw[256];
    __shared__ float sc[1024];
    __shared__ float pl[256];
    __shared__ float red[40];

    aw[tid] = attn_w[tid];
    __syncthreads();

    const float* zb = z1 + (ll)b * 1024 * 256;

    for (int it = 0; it < 128; it++) {
        int t = it * 8 + wrp;
        const float* zr = zb + (ll)t * 256;
        float p = 0.0f;
#pragma unroll
        for (int q = 0; q < 8; q++)
            p = fmaf(zr[lane + 32 * q], aw[lane + 32 * q], p);
#pragma unroll
        for (int o = 16; o; o >>= 1) p += __shfl_down_sync(0xffffffffu, p, o);
        if (lane == 0) sc[t] = p + attn_b[0];
    }
    __syncthreads();

    float mx = -1e30f;
    for (int t = tid; t < 1024; t += 256) mx = fmaxf(mx, sc[t]);
#pragma unroll
    for (int o = 16; o; o >>= 1) mx = fmaxf(mx, __shfl_down_sync(0xffffffffu, mx, o));
    if (lane == 0) red[wrp] = mx;
    __syncthreads();
    if (tid == 0) {
        float m = red[0];
        for (int i = 1; i < 8; i++) m = fmaxf(m, red[i]);
        red[32] = m;
    }
    __syncthreads();
    mx = red[32];
    float s = 0.0f;
    for (int t = tid; t < 1024; t += 256) {
        float e = __expf(sc[t] - mx);
        sc[t] = e;
        s += e;
    }
#pragma unroll
    for (int o = 16; o; o >>= 1) s += __shfl_down_sync(0xffffffffu, s, o);
    if (lane == 0) red[wrp] = s;
    __syncthreads();
    if (tid == 0) {
        float m = 0.0f;
        for (int i = 0; i < 8; i++) m += red[i];
        red[33] = __fdividef(1.0f, m);
    }
    __syncthreads();
    const float inv = red[33];

    float ac0 = 0.0f, ac1 = 0.0f, ac2 = 0.0f, ac3 = 0.0f;
    for (int t = 0; t < 1024; t += 4) {
        ac0 = fmaf(sc[t + 0], zb[(ll)(t + 0) * 256 + tid], ac0);
        ac1 = fmaf(sc[t + 1], zb[(ll)(t + 1) * 256 + tid], ac1);
        ac2 = fmaf(sc[t + 2], zb[(ll)(t + 2) * 256 + tid], ac2);
        ac3 = fmaf(sc[t + 3], zb[(ll)(t + 3) * 256 + tid], ac3);
    }
    pl[tid] = ((ac0 + ac1) + (ac2 + ac3)) * inv;
    __syncthreads();

    if (wrp < 7) {
        const float* wv;
        float bias2;
        int k = motor_k[b];
        if (wrp < 5) {
            wv = motor_w + wrp * 256;
            bias2 = motor_b[wrp];
        } else {
            int c = wrp - 5;
            wv = state_w + (k * 2 + c) * 256;
            bias2 = state_b[k * 2 + c];
        }
        float p = 0.0f;
#pragma unroll
        for (int q = 0; q < 8; q++)
            p = fmaf(pl[lane + 32 * q], wv[lane + 32 * q], p);
#pragma unroll
        for (int o = 16; o; o >>= 1) p += __shfl_down_sync(0xffffffffu, p, o);
        if (lane == 0) {
            if (wrp < 5) out[b * 5 + wrp] = p + bias2;
            else         out[320 + b * 2 + (wrp - 5)] = p + bias2;
        }
    }
}

// ---------------- launcher ----------------
extern "C" void kernel_launch(void* const* d_in, const int* in_sizes, int n_in,
                              void* d_out, int out_size)
{
    const float* x        = (const float*)d_in[0];
    const int*   motor_k  = (const int*)d_in[1];
    const float* wih_l0f  = (const float*)d_in[2];
    const float* whh_l0f  = (const float*)d_in[3];
    const float* bih_l0f  = (const float*)d_in[4];
    const float* bhh_l0f  = (const float*)d_in[5];
    const float* wih_l0b  = (const float*)d_in[6];
    const float* whh_l0b  = (const float*)d_in[7];
    const float* bih_l0b  = (const float*)d_in[8];
    const float* bhh_l0b  = (const float*)d_in[9];
    const float* wih_l1f  = (const float*)d_in[10];
    const float* whh_l1f  = (const float*)d_in[11];
    const float* bih_l1f  = (const float*)d_in[12];
    const float* bhh_l1f  = (const float*)d_in[13];
    const float* wih_l1b  = (const float*)d_in[14];
    const float* whh_l1b  = (const float*)d_in[15];
    const float* bih_l1b  = (const float*)d_in[16];
    const float* bhh_l1b  = (const float*)d_in[17];
    const float* attn_w   = (const float*)d_in[18];
    const float* attn_b   = (const float*)d_in[19];
    const float* motor_w  = (const float*)d_in[20];
    const float* motor_b  = (const float*)d_in[21];
    const float* state_w  = (const float*)d_in[22];
    const float* state_b  = (const float*)d_in[23];

    float *gif, *gib, *z0, *z1;
    cudaGetSymbolAddress((void**)&gif, g_gi_f);
    cudaGetSymbolAddress((void**)&gib, g_gi_b);
    cudaGetSymbolAddress((void**)&z0, g_z0);
    cudaGetSymbolAddress((void**)&z1, g_z1);

    dim3 gb(3, 512, 2);   // N/128, M/128, dirs

    // layer 0
    gemm2<<<gb, 256>>>(x, wih_l0f, wih_l0b, bih_l0f, bih_l0b, gif, gib, 64);
    gru_scan<<<128, 768>>>(gif, gib, whh_l0f, bhh_l0f, whh_l0b, bhh_l0b, z0);
    // layer 1
    gemm2<<<gb, 256>>>(z0, wih_l1f, wih_l1b, bih_l1f, bih_l1b, gif, gib, 256);
    gru_scan<<<128, 768>>>(gif, gib, whh_l1f, bhh_l1f, whh_l1b, bhh_l1b, z1);
    // pooling + heads
    pool_heads<<<64, 256>>>(z1, attn_w, attn_b, motor_w, motor_b,
                            state_w, state_b, motor_k, (float*)d_out);
}

// round 6
// speedup vs baseline: 1.3992x; 1.2285x over previous
#include <cuda_runtime.h>

typedef unsigned long long u64;
typedef long long ll;

// ---------------- scratch (no allocations allowed) ----------------
__device__ float g_gi_f[64 * 1024 * 384];
__device__ float g_gi_b[64 * 1024 * 384];
__device__ float g_z0[64 * 1024 * 256];
__device__ float g_z1[64 * 1024 * 256];

// ---------------- f32x2 helpers ----------------
__device__ __forceinline__ u64 ffma2(u64 a, u64 b, u64 c) {
    u64 d;
    asm("fma.rn.f32x2 %0, %1, %2, %3;" : "=l"(d) : "l"(a), "l"(b), "l"(c));
    return d;
}
__device__ __forceinline__ u64 addf2(u64 a, u64 b) {
    u64 d;
    asm("add.rn.f32x2 %0, %1, %2;" : "=l"(d) : "l"(a), "l"(b));
    return d;
}
__device__ __forceinline__ u64 pack2(float lo, float hi) {
    u64 r;
    asm("mov.b64 %0, {%1, %2};" : "=l"(r) : "f"(lo), "f"(hi));
    return r;
}
__device__ __forceinline__ float2 unpack2(u64 v) {
    float2 f;
    asm("mov.b64 {%0, %1}, %2;" : "=f"(f.x), "=f"(f.y) : "l"(v));
    return f;
}

__device__ __forceinline__ float tanh_mufu(float x) {
    float y;
    asm("tanh.approx.f32 %0, %1;" : "=f"(y) : "f"(x));
    return y;
}
__device__ __forceinline__ float sig_mufu(float x) {
    return fmaf(0.5f, tanh_mufu(0.5f * x), 0.5f);
}

// ---------------- GEMM: C[M,384] = A[M,K] @ W[384,K]^T + bias ----------------
// (R2-proven) BM=128, BN=128, BK=16, 256 threads, 8x8 per thread via f32x2
// n-pairs; A duplicated into (a,a) pairs in registers; W transposed in smem.
__global__ __launch_bounds__(256, 2) void gemm2(
    const float* __restrict__ A,
    const float* __restrict__ Wf, const float* __restrict__ Wb,
    const float* __restrict__ bf, const float* __restrict__ bb,
    float* __restrict__ Cf, float* __restrict__ Cb,
    int K)
{
    const int N = 384;
    const float* W    = blockIdx.z ? Wb : Wf;
    const float* bias = blockIdx.z ? bb : bf;
    float*       C    = blockIdx.z ? Cb : Cf;

    const int mBase = blockIdx.y * 128;
    const int nBase = blockIdx.x * 128;
    const int tid = threadIdx.x;
    const int tx = tid & 15;
    const int ty = tid >> 4;
    const int m0 = ty * 8;
    const int n0 = tx * 8;

    __shared__ float As[16][132];
    __shared__ float Wt[16][132];

    u64 acc[8][4];
#pragma unroll
    for (int mi = 0; mi < 8; mi++)
#pragma unroll
        for (int nj = 0; nj < 4; nj++) acc[mi][nj] = 0ULL;

    const int la_m = tid >> 1;
    const int la_k = (tid & 1) * 8;

    const float* Ap = A + (ll)(mBase + la_m) * K + la_k;
    const float* Wp = W + (ll)(nBase + la_m) * K + la_k;

    for (int k0 = 0; k0 < K; k0 += 16) {
        float4 a0 = *(const float4*)(Ap + k0);
        float4 a1 = *(const float4*)(Ap + k0 + 4);
        float4 w0 = *(const float4*)(Wp + k0);
        float4 w1 = *(const float4*)(Wp + k0 + 4);
        __syncthreads();
        As[la_k + 0][la_m] = a0.x;
        As[la_k + 1][la_m] = a0.y;
        As[la_k + 2][la_m] = a0.z;
        As[la_k + 3][la_m] = a0.w;
        As[la_k + 4][la_m] = a1.x;
        As[la_k + 5][la_m] = a1.y;
        As[la_k + 6][la_m] = a1.z;
        As[la_k + 7][la_m] = a1.w;
        Wt[la_k + 0][la_m] = w0.x;
        Wt[la_k + 1][la_m] = w0.y;
        Wt[la_k + 2][la_m] = w0.z;
        Wt[la_k + 3][la_m] = w0.w;
        Wt[la_k + 4][la_m] = w1.x;
        Wt[la_k + 5][la_m] = w1.y;
        Wt[la_k + 6][la_m] = w1.z;
        Wt[la_k + 7][la_m] = w1.w;
        __syncthreads();
#pragma unroll
        for (int k = 0; k < 16; k++) {
            float4 aL = *(const float4*)&As[k][m0];
            float4 aH = *(const float4*)&As[k][m0 + 4];
            u64 am[8];
            am[0] = pack2(aL.x, aL.x);
            am[1] = pack2(aL.y, aL.y);
            am[2] = pack2(aL.z, aL.z);
            am[3] = pack2(aL.w, aL.w);
            am[4] = pack2(aH.x, aH.x);
            am[5] = pack2(aH.y, aH.y);
            am[6] = pack2(aH.z, aH.z);
            am[7] = pack2(aH.w, aH.w);
            ulonglong2 b01 = *(const ulonglong2*)&Wt[k][n0];
            ulonglong2 b23 = *(const ulonglong2*)&Wt[k][n0 + 4];
            u64 bn[4] = { b01.x, b01.y, b23.x, b23.y };
#pragma unroll
            for (int mi = 0; mi < 8; mi++)
#pragma unroll
                for (int nj = 0; nj < 4; nj++)
                    acc[mi][nj] = ffma2(am[mi], bn[nj], acc[mi][nj]);
        }
    }

    ulonglong2 bv01 = *(const ulonglong2*)(bias + nBase + n0);
    ulonglong2 bv23 = *(const ulonglong2*)(bias + nBase + n0 + 4);
#pragma unroll
    for (int mi = 0; mi < 8; mi++) {
        float* row = C + (ll)(mBase + m0 + mi) * N + nBase + n0;
        ulonglong2 v0, v1;
        v0.x = addf2(acc[mi][0], bv01.x);
        v0.y = addf2(acc[mi][1], bv01.y);
        v1.x = addf2(acc[mi][2], bv23.x);
        v1.y = addf2(acc[mi][3], bv23.y);
        *(ulonglong2*)(row)     = v0;
        *(ulonglong2*)(row + 4) = v1;
    }
}

// ---------------- GRU scan: 128 CTAs = 64 batch x 2 dirs; Whh in registers ----
// gi prefetched at DISTANCE 4 via 4x unrolled time loop: body u consumes
// gpre[u] (loaded 4 steps earlier) and immediately reissues gpre[u] for t+4.
__global__ __launch_bounds__(384, 1) void gru_scan(
    const float* __restrict__ gif, const float* __restrict__ gib,
    const float* __restrict__ whf, const float* __restrict__ bhf,
    const float* __restrict__ whb, const float* __restrict__ bhb,
    float* __restrict__ zout /* [64][1024][256] */)
{
    const int b   = blockIdx.x & 63;
    const int dir = blockIdx.x >> 6;
    const float* gi  = dir ? gib : gif;
    const float* whh = dir ? whb : whf;
    const float* bhh = dir ? bhb : bhf;
    const int j = threadIdx.x;   // rows: [0,128)=r, [128,256)=z, [256,384)=n

    u64 w[64];
    {
        const u64* wp = (const u64*)(whh + j * 128);
#pragma unroll
        for (int k = 0; k < 64; k++) w[k] = wp[k];
    }
    const float bh = bhh[j];

    __shared__ __align__(16) float hsm[128];
    __shared__ float rsm[128];
    __shared__ float zsm[128];
    if (j < 128) hsm[j] = 0.0f;
    __syncthreads();

    const int step = dir ? -1 : 1;
    int tt = dir ? 1023 : 0;
    const float* gip = gi + (ll)b * (1024 * 384) + j;
    float* zrow = zout + (ll)b * (1024 * 256) + dir * 128;

    // prime 4-deep prefetch pipeline (wrap-indexed; overruns unused)
    float gpre[4];
#pragma unroll
    for (int d = 0; d < 4; d++)
        gpre[d] = gip[((tt + d * step) & 1023) * 384];

    for (int t = 0; t < 1024; t += 4) {
#pragma unroll
        for (int u = 0; u < 4; u++) {
            float gcur = gpre[u];
            // reissue this slot for step t+u+4 (distance-4 slack)
            gpre[u] = gip[((tt + 4 * step) & 1023) * 384];

            // gh_j = Whh[j,:] . h  (64 FFMA2 in 4 chains; broadcast LDS.128)
            u64 a0 = 0ULL, a1 = 0ULL, a2 = 0ULL, a3 = 0ULL;
            const ulonglong2* hp2 = (const ulonglong2*)hsm;
#pragma unroll
            for (int q = 0; q < 16; q++) {
                ulonglong2 u0 = hp2[2 * q];
                ulonglong2 u1 = hp2[2 * q + 1];
                a0 = ffma2(w[4 * q + 0], u0.x, a0);
                a1 = ffma2(w[4 * q + 1], u0.y, a1);
                a2 = ffma2(w[4 * q + 2], u1.x, a2);
                a3 = ffma2(w[4 * q + 3], u1.y, a3);
            }
            float2 f0 = unpack2(a0), f1 = unpack2(a1);
            float2 f2 = unpack2(a2), f3 = unpack2(a3);
            float gh = ((f0.x + f0.y) + (f1.x + f1.y)) +
                       ((f2.x + f2.y) + (f3.x + f3.y)) + bh;

            float hold = 0.0f;
            if (j >= 256) hold = hsm[j - 256];     // preload before barrier
            if (j < 128) {
                rsm[j] = sig_mufu(gcur + gh);
            } else if (j < 256) {
                zsm[j - 128] = sig_mufu(gcur + gh);
            }
            __syncthreads();                       // gates visible
            if (j >= 256) {
                int i = j - 256;
                float n = tanh_mufu(fmaf(rsm[i], gh, gcur));
                float hnew = fmaf(zsm[i], hold - n, n);  // (1-z)n + z h
                hsm[i] = hnew;
                zrow[tt * 256 + i] = hnew;
            }
            __syncthreads();                       // hsm ready for next dot
            tt += step;
        }
    }
}

// ---------------- attention pooling + heads ----------------
__global__ __launch_bounds__(256) void pool_heads(
    const float* __restrict__ z1,
    const float* __restrict__ attn_w, const float* __restrict__ attn_b,
    const float* __restrict__ motor_w, const float* __restrict__ motor_b,
    const float* __restrict__ state_w, const float* __restrict__ state_b,
    const int* __restrict__ motor_k,
    float* __restrict__ out)
{
    const int b = blockIdx.x;
    const int tid = threadIdx.x;
    const int lane = tid & 31;
    const int wrp = tid >> 5;

    __shared__ float aw[256];
    __shared__ float sc[1024];
    __shared__ float pl[256];
    __shared__ float red[40];

    aw[tid] = attn_w[tid];
    __syncthreads();

    const float* zb = z1 + (ll)b * 1024 * 256;

    for (int it = 0; it < 128; it++) {
        int t = it * 8 + wrp;
        const float* zr = zb + (ll)t * 256;
        float p = 0.0f;
#pragma unroll
        for (int q = 0; q < 8; q++)
            p = fmaf(zr[lane + 32 * q], aw[lane + 32 * q], p);
#pragma unroll
        for (int o = 16; o; o >>= 1) p += __shfl_down_sync(0xffffffffu, p, o);
        if (lane == 0) sc[t] = p + attn_b[0];
    }
    __syncthreads();

    float mx = -1e30f;
    for (int t = tid; t < 1024; t += 256) mx = fmaxf(mx, sc[t]);
#pragma unroll
    for (int o = 16; o; o >>= 1) mx = fmaxf(mx, __shfl_down_sync(0xffffffffu, mx, o));
    if (lane == 0) red[wrp] = mx;
    __syncthreads();
    if (tid == 0) {
        float m = red[0];
        for (int i = 1; i < 8; i++) m = fmaxf(m, red[i]);
        red[32] = m;
    }
    __syncthreads();
    mx = red[32];
    float s = 0.0f;
    for (int t = tid; t < 1024; t += 256) {
        float e = __expf(sc[t] - mx);
        sc[t] = e;
        s += e;
    }
#pragma unroll
    for (int o = 16; o; o >>= 1) s += __shfl_down_sync(0xffffffffu, s, o);
    if (lane == 0) red[wrp] = s;
    __syncthreads();
    if (tid == 0) {
        float m = 0.0f;
        for (int i = 0; i < 8; i++) m += red[i];
        red[33] = __fdividef(1.0f, m);
    }
    __syncthreads();
    const float inv = red[33];

    float ac0 = 0.0f, ac1 = 0.0f, ac2 = 0.0f, ac3 = 0.0f;
    for (int t = 0; t < 1024; t += 4) {
        ac0 = fmaf(sc[t + 0], zb[(ll)(t + 0) * 256 + tid], ac0);
        ac1 = fmaf(sc[t + 1], zb[(ll)(t + 1) * 256 + tid], ac1);
        ac2 = fmaf(sc[t + 2], zb[(ll)(t + 2) * 256 + tid], ac2);
        ac3 = fmaf(sc[t + 3], zb[(ll)(t + 3) * 256 + tid], ac3);
    }
    pl[tid] = ((ac0 + ac1) + (ac2 + ac3)) * inv;
    __syncthreads();

    if (wrp < 7) {
        const float* wv;
        float bias2;
        int k = motor_k[b];
        if (wrp < 5) {
            wv = motor_w + wrp * 256;
            bias2 = motor_b[wrp];
        } else {
            int c = wrp - 5;
            wv = state_w + (k * 2 + c) * 256;
            bias2 = state_b[k * 2 + c];
        }
        float p = 0.0f;
#pragma unroll
        for (int q = 0; q < 8; q++)
            p = fmaf(pl[lane + 32 * q], wv[lane + 32 * q], p);
#pragma unroll
        for (int o = 16; o; o >>= 1) p += __shfl_down_sync(0xffffffffu, p, o);
        if (lane == 0) {
            if (wrp < 5) out[b * 5 + wrp] = p + bias2;
            else         out[320 + b * 2 + (wrp - 5)] = p + bias2;
        }
    }
}

// ---------------- launcher ----------------
extern "C" void kernel_launch(void* const* d_in, const int* in_sizes, int n_in,
                              void* d_out, int out_size)
{
    const float* x        = (const float*)d_in[0];
    const int*   motor_k  = (const int*)d_in[1];
    const float* wih_l0f  = (const float*)d_in[2];
    const float* whh_l0f  = (const float*)d_in[3];
    const float* bih_l0f  = (const float*)d_in[4];
    const float* bhh_l0f  = (const float*)d_in[5];
    const float* wih_l0b  = (const float*)d_in[6];
    const float* whh_l0b  = (const float*)d_in[7];
    const float* bih_l0b  = (const float*)d_in[8];
    const float* bhh_l0b  = (const float*)d_in[9];
    const float* wih_l1f  = (const float*)d_in[10];
    const float* whh_l1f  = (const float*)d_in[11];
    const float* bih_l1f  = (const float*)d_in[12];
    const float* bhh_l1f  = (const float*)d_in[13];
    const float* wih_l1b  = (const float*)d_in[14];
    const float* whh_l1b  = (const float*)d_in[15];
    const float* bih_l1b  = (const float*)d_in[16];
    const float* bhh_l1b  = (const float*)d_in[17];
    const float* attn_w   = (const float*)d_in[18];
    const float* attn_b   = (const float*)d_in[19];
    const float* motor_w  = (const float*)d_in[20];
    const float* motor_b  = (const float*)d_in[21];
    const float* state_w  = (const float*)d_in[22];
    const float* state_b  = (const float*)d_in[23];

    float *gif, *gib, *z0, *z1;
    cudaGetSymbolAddress((void**)&gif, g_gi_f);
    cudaGetSymbolAddress((void**)&gib, g_gi_b);
    cudaGetSymbolAddress((void**)&z0, g_z0);
    cudaGetSymbolAddress((void**)&z1, g_z1);

    dim3 gb(3, 512, 2);   // N/128, M/128, dirs

    // layer 0
    gemm2<<<gb, 256>>>(x, wih_l0f, wih_l0b, bih_l0f, bih_l0b, gif, gib, 64);
    gru_scan<<<128, 384>>>(gif, gib, whh_l0f, bhh_l0f, whh_l0b, bhh_l0b, z0);
    // layer 1
    gemm2<<<gb, 256>>>(z0, wih_l1f, wih_l1b, bih_l1f, bih_l1b, gif, gib, 256);
    gru_scan<<<128, 384>>>(gif, gib, whh_l1f, bhh_l1f, whh_l1b, bhh_l1b, z1);
    // pooling + heads
    pool_heads<<<64, 256>>>(z1, attn_w, attn_b, motor_w, motor_b,
                            state_w, state_b, motor_k, (float*)d_out);
}

// round 7
// speedup vs baseline: 1.4066x; 1.0053x over previous
#include <cuda_runtime.h>

typedef unsigned long long u64;
typedef long long ll;

// ---------------- scratch (no allocations allowed) ----------------
__device__ float g_gi_f[64 * 1024 * 384];
__device__ float g_gi_b[64 * 1024 * 384];
__device__ float g_z0[64 * 1024 * 256];
__device__ float g_z1[64 * 1024 * 256];

// ---------------- f32x2 helpers ----------------
__device__ __forceinline__ u64 ffma2(u64 a, u64 b, u64 c) {
    u64 d;
    asm("fma.rn.f32x2 %0, %1, %2, %3;" : "=l"(d) : "l"(a), "l"(b), "l"(c));
    return d;
}
__device__ __forceinline__ u64 addf2(u64 a, u64 b) {
    u64 d;
    asm("add.rn.f32x2 %0, %1, %2;" : "=l"(d) : "l"(a), "l"(b));
    return d;
}
__device__ __forceinline__ u64 pack2(float lo, float hi) {
    u64 r;
    asm("mov.b64 %0, {%1, %2};" : "=l"(r) : "f"(lo), "f"(hi));
    return r;
}
__device__ __forceinline__ float2 unpack2(u64 v) {
    float2 f;
    asm("mov.b64 {%0, %1}, %2;" : "=f"(f.x), "=f"(f.y) : "l"(v));
    return f;
}

__device__ __forceinline__ float tanh_mufu(float x) {
    float y;
    asm("tanh.approx.f32 %0, %1;" : "=f"(y) : "f"(x));
    return y;
}
__device__ __forceinline__ float sig_mufu(float x) {
    return fmaf(0.5f, tanh_mufu(0.5f * x), 0.5f);
}

// ---------------- GEMM: C[M,384] = A[M,K] @ W[384,K]^T + bias ----------------
// BM=128, BN=128, BK=16, 256 threads, 8x8 per thread via f32x2 n-pairs.
// SOFTWARE-PIPELINED: next tile's LDG issues before compute of the current
// tile, so global-load latency hides under ~4000 cyc of FFMA2 work.
__global__ __launch_bounds__(256, 2) void gemm2(
    const float* __restrict__ A,
    const float* __restrict__ Wf, const float* __restrict__ Wb,
    const float* __restrict__ bf, const float* __restrict__ bb,
    float* __restrict__ Cf, float* __restrict__ Cb,
    int K)
{
    const int N = 384;
    const float* W    = blockIdx.z ? Wb : Wf;
    const float* bias = blockIdx.z ? bb : bf;
    float*       C    = blockIdx.z ? Cb : Cf;

    const int mBase = blockIdx.y * 128;
    const int nBase = blockIdx.x * 128;
    const int tid = threadIdx.x;
    const int tx = tid & 15;
    const int ty = tid >> 4;
    const int m0 = ty * 8;
    const int n0 = tx * 8;

    __shared__ float As[16][132];
    __shared__ float Wt[16][132];

    u64 acc[8][4];
#pragma unroll
    for (int mi = 0; mi < 8; mi++)
#pragma unroll
        for (int nj = 0; nj < 4; nj++) acc[mi][nj] = 0ULL;

    const int la_m = tid >> 1;
    const int la_k = (tid & 1) * 8;

    const float* Ap = A + (ll)(mBase + la_m) * K + la_k;
    const float* Wp = W + (ll)(nBase + la_m) * K + la_k;

    // prologue: load tile 0 into registers
    float4 a0 = *(const float4*)(Ap);
    float4 a1 = *(const float4*)(Ap + 4);
    float4 w0 = *(const float4*)(Wp);
    float4 w1 = *(const float4*)(Wp + 4);

    for (int k0 = 0; k0 < K; k0 += 16) {
        __syncthreads();                    // smem free (prev compute done)
        As[la_k + 0][la_m] = a0.x;
        As[la_k + 1][la_m] = a0.y;
        As[la_k + 2][la_m] = a0.z;
        As[la_k + 3][la_m] = a0.w;
        As[la_k + 4][la_m] = a1.x;
        As[la_k + 5][la_m] = a1.y;
        As[la_k + 6][la_m] = a1.z;
        As[la_k + 7][la_m] = a1.w;
        Wt[la_k + 0][la_m] = w0.x;
        Wt[la_k + 1][la_m] = w0.y;
        Wt[la_k + 2][la_m] = w0.z;
        Wt[la_k + 3][la_m] = w0.w;
        Wt[la_k + 4][la_m] = w1.x;
        Wt[la_k + 5][la_m] = w1.y;
        Wt[la_k + 6][la_m] = w1.z;
        Wt[la_k + 7][la_m] = w1.w;
        __syncthreads();                    // tile visible

        if (k0 + 16 < K) {                  // prefetch next tile under compute
            a0 = *(const float4*)(Ap + k0 + 16);
            a1 = *(const float4*)(Ap + k0 + 20);
            w0 = *(const float4*)(Wp + k0 + 16);
            w1 = *(const float4*)(Wp + k0 + 20);
        }

#pragma unroll
        for (int k = 0; k < 16; k++) {
            float4 aL = *(const float4*)&As[k][m0];
            float4 aH = *(const float4*)&As[k][m0 + 4];
            u64 am[8];
            am[0] = pack2(aL.x, aL.x);
            am[1] = pack2(aL.y, aL.y);
            am[2] = pack2(aL.z, aL.z);
            am[3] = pack2(aL.w, aL.w);
            am[4] = pack2(aH.x, aH.x);
            am[5] = pack2(aH.y, aH.y);
            am[6] = pack2(aH.z, aH.z);
            am[7] = pack2(aH.w, aH.w);
            ulonglong2 b01 = *(const ulonglong2*)&Wt[k][n0];
            ulonglong2 b23 = *(const ulonglong2*)&Wt[k][n0 + 4];
            u64 bn[4] = { b01.x, b01.y, b23.x, b23.y };
#pragma unroll
            for (int mi = 0; mi < 8; mi++)
#pragma unroll
                for (int nj = 0; nj < 4; nj++)
                    acc[mi][nj] = ffma2(am[mi], bn[nj], acc[mi][nj]);
        }
    }

    ulonglong2 bv01 = *(const ulonglong2*)(bias + nBase + n0);
    ulonglong2 bv23 = *(const ulonglong2*)(bias + nBase + n0 + 4);
#pragma unroll
    for (int mi = 0; mi < 8; mi++) {
        float* row = C + (ll)(mBase + m0 + mi) * N + nBase + n0;
        ulonglong2 v0, v1;
        v0.x = addf2(acc[mi][0], bv01.x);
        v0.y = addf2(acc[mi][1], bv01.y);
        v1.x = addf2(acc[mi][2], bv23.x);
        v1.y = addf2(acc[mi][3], bv23.y);
        *(ulonglong2*)(row)     = v0;
        *(ulonglong2*)(row + 4) = v1;
    }
}

// ---------------- GRU scan (R6-proven): distance-4 prefetch ----------------
__global__ __launch_bounds__(384, 1) void gru_scan(
    const float* __restrict__ gif, const float* __restrict__ gib,
    const float* __restrict__ whf, const float* __restrict__ bhf,
    const float* __restrict__ whb, const float* __restrict__ bhb,
    float* __restrict__ zout /* [64][1024][256] */)
{
    const int b   = blockIdx.x & 63;
    const int dir = blockIdx.x >> 6;
    const float* gi  = dir ? gib : gif;
    const float* whh = dir ? whb : whf;
    const float* bhh = dir ? bhb : bhf;
    const int j = threadIdx.x;   // rows: [0,128)=r, [128,256)=z, [256,384)=n

    u64 w[64];
    {
        const u64* wp = (const u64*)(whh + j * 128);
#pragma unroll
        for (int k = 0; k < 64; k++) w[k] = wp[k];
    }
    const float bh = bhh[j];

    __shared__ __align__(16) float hsm[128];
    __shared__ float rsm[128];
    __shared__ float zsm[128];
    if (j < 128) hsm[j] = 0.0f;
    __syncthreads();

    const int step = dir ? -1 : 1;
    int tt = dir ? 1023 : 0;
    const float* gip = gi + (ll)b * (1024 * 384) + j;
    float* zrow = zout + (ll)b * (1024 * 256) + dir * 128;

    float gpre[4];
#pragma unroll
    for (int d = 0; d < 4; d++)
        gpre[d] = gip[((tt + d * step) & 1023) * 384];

    for (int t = 0; t < 1024; t += 4) {
#pragma unroll
        for (int u = 0; u < 4; u++) {
            float gcur = gpre[u];
            gpre[u] = gip[((tt + 4 * step) & 1023) * 384];

            u64 a0 = 0ULL, a1 = 0ULL, a2 = 0ULL, a3 = 0ULL;
            const ulonglong2* hp2 = (const ulonglong2*)hsm;
#pragma unroll
            for (int q = 0; q < 16; q++) {
                ulonglong2 u0 = hp2[2 * q];
                ulonglong2 u1 = hp2[2 * q + 1];
                a0 = ffma2(w[4 * q + 0], u0.x, a0);
                a1 = ffma2(w[4 * q + 1], u0.y, a1);
                a2 = ffma2(w[4 * q + 2], u1.x, a2);
                a3 = ffma2(w[4 * q + 3], u1.y, a3);
            }
            float2 f0 = unpack2(a0), f1 = unpack2(a1);
            float2 f2 = unpack2(a2), f3 = unpack2(a3);
            float gh = ((f0.x + f0.y) + (f1.x + f1.y)) +
                       ((f2.x + f2.y) + (f3.x + f3.y)) + bh;

            float hold = 0.0f;
            if (j >= 256) hold = hsm[j - 256];
            if (j < 128) {
                rsm[j] = sig_mufu(gcur + gh);
            } else if (j < 256) {
                zsm[j - 128] = sig_mufu(gcur + gh);
            }
            __syncthreads();
            if (j >= 256) {
                int i = j - 256;
                float n = tanh_mufu(fmaf(rsm[i], gh, gcur));
                float hnew = fmaf(zsm[i], hold - n, n);
                hsm[i] = hnew;
                zrow[tt * 256 + i] = hnew;
            }
            __syncthreads();
            tt += step;
        }
    }
}

// ---------------- attention pooling + heads ----------------
__global__ __launch_bounds__(256) void pool_heads(
    const float* __restrict__ z1,
    const float* __restrict__ attn_w, const float* __restrict__ attn_b,
    const float* __restrict__ motor_w, const float* __restrict__ motor_b,
    const float* __restrict__ state_w, const float* __restrict__ state_b,
    const int* __restrict__ motor_k,
    float* __restrict__ out)
{
    const int b = blockIdx.x;
    const int tid = threadIdx.x;
    const int lane = tid & 31;
    const int wrp = tid >> 5;

    __shared__ float aw[256];
    __shared__ float sc[1024];
    __shared__ float pl[256];
    __shared__ float red[40];

    aw[tid] = attn_w[tid];
    __syncthreads();

    const float* zb = z1 + (ll)b * 1024 * 256;

    for (int it = 0; it < 128; it++) {
        int t = it * 8 + wrp;
        const float* zr = zb + (ll)t * 256;
        float p = 0.0f;
#pragma unroll
        for (int q = 0; q < 8; q++)
            p = fmaf(zr[lane + 32 * q], aw[lane + 32 * q], p);
#pragma unroll
        for (int o = 16; o; o >>= 1) p += __shfl_down_sync(0xffffffffu, p, o);
        if (lane == 0) sc[t] = p + attn_b[0];
    }
    __syncthreads();

    float mx = -1e30f;
    for (int t = tid; t < 1024; t += 256) mx = fmaxf(mx, sc[t]);
#pragma unroll
    for (int o = 16; o; o >>= 1) mx = fmaxf(mx, __shfl_down_sync(0xffffffffu, mx, o));
    if (lane == 0) red[wrp] = mx;
    __syncthreads();
    if (tid == 0) {
        float m = red[0];
        for (int i = 1; i < 8; i++) m = fmaxf(m, red[i]);
        red[32] = m;
    }
    __syncthreads();
    mx = red[32];
    float s = 0.0f;
    for (int t = tid; t < 1024; t += 256) {
        float e = __expf(sc[t] - mx);
        sc[t] = e;
        s += e;
    }
#pragma unroll
    for (int o = 16; o; o >>= 1) s += __shfl_down_sync(0xffffffffu, s, o);
    if (lane == 0) red[wrp] = s;
    __syncthreads();
    if (tid == 0) {
        float m = 0.0f;
        for (int i = 0; i < 8; i++) m += red[i];
        red[33] = __fdividef(1.0f, m);
    }
    __syncthreads();
    const float inv = red[33];

    float ac0 = 0.0f, ac1 = 0.0f, ac2 = 0.0f, ac3 = 0.0f;
    for (int t = 0; t < 1024; t += 4) {
        ac0 = fmaf(sc[t + 0], zb[(ll)(t + 0) * 256 + tid], ac0);
        ac1 = fmaf(sc[t + 1], zb[(ll)(t + 1) * 256 + tid], ac1);
        ac2 = fmaf(sc[t + 2], zb[(ll)(t + 2) * 256 + tid], ac2);
        ac3 = fmaf(sc[t + 3], zb[(ll)(t + 3) * 256 + tid], ac3);
    }
    pl[tid] = ((ac0 + ac1) + (ac2 + ac3)) * inv;
    __syncthreads();

    if (wrp < 7) {
        const float* wv;
        float bias2;
        int k = motor_k[b];
        if (wrp < 5) {
            wv = motor_w + wrp * 256;
            bias2 = motor_b[wrp];
        } else {
            int c = wrp - 5;
            wv = state_w + (k * 2 + c) * 256;
            bias2 = state_b[k * 2 + c];
        }
        float p = 0.0f;
#pragma unroll
        for (int q = 0; q < 8; q++)
            p = fmaf(pl[lane + 32 * q], wv[lane + 32 * q], p);
#pragma unroll
        for (int o = 16; o; o >>= 1) p += __shfl_down_sync(0xffffffffu, p, o);
        if (lane == 0) {
            if (wrp < 5) out[b * 5 + wrp] = p + bias2;
            else         out[320 + b * 2 + (wrp - 5)] = p + bias2;
        }
    }
}

// ---------------- launcher ----------------
extern "C" void kernel_launch(void* const* d_in, const int* in_sizes, int n_in,
                              void* d_out, int out_size)
{
    const float* x        = (const float*)d_in[0];
    const int*   motor_k  = (const int*)d_in[1];
    const float* wih_l0f  = (const float*)d_in[2];
    const float* whh_l0f  = (const float*)d_in[3];
    const float* bih_l0f  = (const float*)d_in[4];
    const float* bhh_l0f  = (const float*)d_in[5];
    const float* wih_l0b  = (const float*)d_in[6];
    const float* whh_l0b  = (const float*)d_in[7];
    const float* bih_l0b  = (const float*)d_in[8];
    const float* bhh_l0b  = (const float*)d_in[9];
    const float* wih_l1f  = (const float*)d_in[10];
    const float* whh_l1f  = (const float*)d_in[11];
    const float* bih_l1f  = (const float*)d_in[12];
    const float* bhh_l1f  = (const float*)d_in[13];
    const float* wih_l1b  = (const float*)d_in[14];
    const float* whh_l1b  = (const float*)d_in[15];
    const float* bih_l1b  = (const float*)d_in[16];
    const float* bhh_l1b  = (const float*)d_in[17];
    const float* attn_w   = (const float*)d_in[18];
    const float* attn_b   = (const float*)d_in[19];
    const float* motor_w  = (const float*)d_in[20];
    const float* motor_b  = (const float*)d_in[21];
    const float* state_w  = (const float*)d_in[22];
    const float* state_b  = (const float*)d_in[23];

    float *gif, *gib, *z0, *z1;
    cudaGetSymbolAddress((void**)&gif, g_gi_f);
    cudaGetSymbolAddress((void**)&gib, g_gi_b);
    cudaGetSymbolAddress((void**)&z0, g_z0);
    cudaGetSymbolAddress((void**)&z1, g_z1);

    dim3 gb(3, 512, 2);   // N/128, M/128, dirs

    // layer 0
    gemm2<<<gb, 256>>>(x, wih_l0f, wih_l0b, bih_l0f, bih_l0b, gif, gib, 64);
    gru_scan<<<128, 384>>>(gif, gib, whh_l0f, bhh_l0f, whh_l0b, bhh_l0b, z0);
    // layer 1
    gemm2<<<gb, 256>>>(z0, wih_l1f, wih_l1b, bih_l1f, bih_l1b, gif, gib, 256);
    gru_scan<<<128, 384>>>(gif, gib, whh_l1f, bhh_l1f, whh_l1b, bhh_l1b, z1);
    // pooling + heads
    pool_heads<<<64, 256>>>(z1, attn_w, attn_b, motor_w, motor_b,
                            state_w, state_b, motor_k, (float*)d_out);
}

// round 9
// speedup vs baseline: 1.6173x; 1.1498x over previous
#include <cuda_runtime.h>
#include <cuda_bf16.h>

typedef unsigned long long u64;
typedef long long ll;
typedef unsigned int u32;

// ---------------- scratch (no allocations allowed) ----------------
__device__ float g_gi_f[64 * 1024 * 384];
__device__ float g_gi_b[64 * 1024 * 384];
__device__ float g_z0[64 * 1024 * 256];
__device__ float g_z1[64 * 1024 * 256];
__device__ __nv_bfloat16 g_ahi[64 * 1024 * 256];
__device__ __nv_bfloat16 g_alo[64 * 1024 * 256];
__device__ __nv_bfloat16 g_whi_f[384 * 256];
__device__ __nv_bfloat16 g_wlo_f[384 * 256];
__device__ __nv_bfloat16 g_whi_b[384 * 256];
__device__ __nv_bfloat16 g_wlo_b[384 * 256];

// ---------------- f32x2 helpers (scan) ----------------
__device__ __forceinline__ u64 ffma2(u64 a, u64 b, u64 c) {
    u64 d;
    asm("fma.rn.f32x2 %0, %1, %2, %3;" : "=l"(d) : "l"(a), "l"(b), "l"(c));
    return d;
}
__device__ __forceinline__ float2 unpack2(u64 v) {
    float2 f;
    asm("mov.b64 {%0, %1}, %2;" : "=f"(f.x), "=f"(f.y) : "l"(v));
    return f;
}
__device__ __forceinline__ float tanh_mufu(float x) {
    float y;
    asm("tanh.approx.f32 %0, %1;" : "=f"(y) : "f"(x));
    return y;
}
__device__ __forceinline__ float sig_mufu(float x) {
    return fmaf(0.5f, tanh_mufu(0.5f * x), 0.5f);
}

// ---------------- mma.sync helpers (base ISA, works on compute_103) --------
__device__ __forceinline__ u32 smem_u32(const void* p) {
    u32 a;
    asm("{ .reg .u64 t; cvta.to.shared.u64 t, %1; cvt.u32.u64 %0, t; }"
        : "=r"(a) : "l"(p));
    return a;
}
__device__ __forceinline__ void ldsm_x4(u32* r, u32 addr) {
    asm volatile("ldmatrix.sync.aligned.m8n8.x4.shared.b16 {%0,%1,%2,%3}, [%4];"
                 : "=r"(r[0]), "=r"(r[1]), "=r"(r[2]), "=r"(r[3]) : "r"(addr));
}
__device__ __forceinline__ void ldsm_x2(u32* r, u32 addr) {
    asm volatile("ldmatrix.sync.aligned.m8n8.x2.shared.b16 {%0,%1}, [%2];"
                 : "=r"(r[0]), "=r"(r[1]) : "r"(addr));
}
__device__ __forceinline__ void mma16816(float* c, const u32* a, const u32* b) {
    asm volatile(
        "mma.sync.aligned.m16n8k16.row.col.f32.bf16.bf16.f32 "
        "{%0,%1,%2,%3}, {%4,%5,%6,%7}, {%8,%9}, {%0,%1,%2,%3};"
        : "+f"(c[0]), "+f"(c[1]), "+f"(c[2]), "+f"(c[3])
        : "r"(a[0]), "r"(a[1]), "r"(a[2]), "r"(a[3]), "r"(b[0]), "r"(b[1]));
}

// ---------------- bf16 hi/lo split conversion ----------------
__global__ void split_bf16(const float* __restrict__ a,
                           __nv_bfloat16* __restrict__ hi,
                           __nv_bfloat16* __restrict__ lo, int n4)
{
    int i = blockIdx.x * blockDim.x + threadIdx.x;
    if (i >= n4) return;
    float4 v = ((const float4*)a)[i];
    __nv_bfloat16 h0 = __float2bfloat16(v.x);
    __nv_bfloat16 h1 = __float2bfloat16(v.y);
    __nv_bfloat16 h2 = __float2bfloat16(v.z);
    __nv_bfloat16 h3 = __float2bfloat16(v.w);
    __nv_bfloat16 l0 = __float2bfloat16(v.x - __bfloat162float(h0));
    __nv_bfloat16 l1 = __float2bfloat16(v.y - __bfloat162float(h1));
    __nv_bfloat16 l2 = __float2bfloat16(v.z - __bfloat162float(h2));
    __nv_bfloat16 l3 = __float2bfloat16(v.w - __bfloat162float(h3));
    ((__nv_bfloat162*)hi)[2 * i]     = __nv_bfloat162(h0, h1);
    ((__nv_bfloat162*)hi)[2 * i + 1] = __nv_bfloat162(h2, h3);
    ((__nv_bfloat162*)lo)[2 * i]     = __nv_bfloat162(l0, l1);
    ((__nv_bfloat162*)lo)[2 * i + 1] = __nv_bfloat162(l2, l3);
}

// ---------------- tensor-core GEMM via mma.sync ----------------
// C[M,384] = A[M,K] @ W[384,K]^T + bias, fp32 out.
// bf16 3-term split: Ahi*Whi + Ahi*Wlo + Alo*Whi (lo*lo dropped, ~2^-16 rel).
// BM=128, BN=128, BK=32; 256 thr, 8 warps in 2(m) x 4(n), warp tile 64x32.
static constexpr int LDS = 40;   // padded row: 40 bf16 = 80B (bank-safe)

__global__ void __launch_bounds__(256, 1) mma_gemm(
    const __nv_bfloat16* __restrict__ ahi, const __nv_bfloat16* __restrict__ alo,
    const __nv_bfloat16* __restrict__ whif, const __nv_bfloat16* __restrict__ wlof,
    const __nv_bfloat16* __restrict__ whib, const __nv_bfloat16* __restrict__ wlob,
    const float* __restrict__ biasf, const float* __restrict__ biasb,
    float* __restrict__ cf, float* __restrict__ cb, int K)
{
    const int dir = blockIdx.z;
    const __nv_bfloat16* whi = dir ? whib : whif;
    const __nv_bfloat16* wlo = dir ? wlob : wlof;
    const float* bias = dir ? biasb : biasf;
    float* C = dir ? cb : cf;

    const int nBase = blockIdx.x * 128;
    const int mBase = blockIdx.y * 128;
    const int tid = threadIdx.x;
    const int lane = tid & 31;
    const int warp = tid >> 5;
    const int mw = (warp & 1) * 64;     // warp m-offset
    const int nw = (warp >> 1) * 32;    // warp n-offset

    __shared__ __nv_bfloat16 sAhi[128 * LDS];
    __shared__ __nv_bfloat16 sAlo[128 * LDS];
    __shared__ __nv_bfloat16 sWhi[128 * LDS];
    __shared__ __nv_bfloat16 sWlo[128 * LDS];

    float acc[4][4][4];
#pragma unroll
    for (int i = 0; i < 4; i++)
#pragma unroll
        for (int j = 0; j < 4; j++)
#pragma unroll
            for (int r = 0; r < 4; r++) acc[i][j][r] = 0.0f;

    const u32 bAhi = smem_u32(sAhi), bAlo = smem_u32(sAlo);
    const u32 bWhi = smem_u32(sWhi), bWlo = smem_u32(sWlo);

    // ldmatrix lane addressing (element offsets within tile)
    const u32 a_row = mw + (lane & 15);
    const u32 a_col = (lane >> 4) * 8;          // +k16 at use
    const u32 b_row = nw + (lane & 7);
    const u32 b_col = ((lane >> 3) & 1) * 8;    // +k16 at use (lanes 0-15 used)

    const int nChunks = K >> 5;
    for (int c = 0; c < nChunks; c++) {
        const int kc = c << 5;
        __syncthreads();
        // stage 4 tiles: 128 rows x 32 bf16 each; 1024 u64 per tile
#pragma unroll
        for (int it = 0; it < 4; it++) {
            int u = it * 256 + tid;
            int row = u >> 3, seg = u & 7;
            u32 so = (u32)(row * LDS + seg * 4);
            ll asrc = (ll)(mBase + row) * K + kc + seg * 4;
            ll wsrc = (ll)(nBase + row) * K + kc + seg * 4;
            *(u64*)(sAhi + so) = *(const u64*)(ahi + asrc);
            *(u64*)(sAlo + so) = *(const u64*)(alo + asrc);
            *(u64*)(sWhi + so) = *(const u64*)(whi + wsrc);
            *(u64*)(sWlo + so) = *(const u64*)(wlo + wsrc);
        }
        __syncthreads();

#pragma unroll
        for (int ks = 0; ks < 2; ks++) {
            const u32 k16 = ks * 16;
            u32 fahi[4][4], falo[4][4];
#pragma unroll
            for (int ms = 0; ms < 4; ms++) {
                u32 off = ((a_row + ms * 16) * LDS + a_col + k16) * 2;
                ldsm_x4(fahi[ms], bAhi + off);
                ldsm_x4(falo[ms], bAlo + off);
            }
            u32 fbhi[4][2], fblo[4][2];
#pragma unroll
            for (int ns = 0; ns < 4; ns++) {
                u32 off = ((b_row + ns * 8) * LDS + b_col + k16) * 2;
                ldsm_x2(fbhi[ns], bWhi + off);
                ldsm_x2(fblo[ns], bWlo + off);
            }
#pragma unroll
            for (int ms = 0; ms < 4; ms++)
#pragma unroll
                for (int ns = 0; ns < 4; ns++) {
                    mma16816(acc[ms][ns], fahi[ms], fbhi[ns]);
                    mma16816(acc[ms][ns], fahi[ms], fblo[ns]);
                    mma16816(acc[ms][ns], falo[ms], fbhi[ns]);
                }
        }
    }

    // epilogue: add bias, store fp32
    const int cbase = nBase + nw + 2 * (lane & 3);
    float2 bv[4];
#pragma unroll
    for (int ns = 0; ns < 4; ns++) {
        bv[ns].x = __ldg(&bias[cbase + ns * 8]);
        bv[ns].y = __ldg(&bias[cbase + ns * 8 + 1]);
    }
#pragma unroll
    for (int ms = 0; ms < 4; ms++) {
        int r0 = mBase + mw + ms * 16 + (lane >> 2);
#pragma unroll
        for (int ns = 0; ns < 4; ns++) {
            int col = cbase + ns * 8;
            float2 lo2, hi2;
            lo2.x = acc[ms][ns][0] + bv[ns].x;
            lo2.y = acc[ms][ns][1] + bv[ns].y;
            hi2.x = acc[ms][ns][2] + bv[ns].x;
            hi2.y = acc[ms][ns][3] + bv[ns].y;
            *(float2*)(C + (ll)r0 * 384 + col)       = lo2;
            *(float2*)(C + (ll)(r0 + 8) * 384 + col) = hi2;
        }
    }
}

// ---------------- GRU scan (R6-proven): distance-4 prefetch ----------------
__global__ __launch_bounds__(384, 1) void gru_scan(
    const float* __restrict__ gif, const float* __restrict__ gib,
    const float* __restrict__ whf, const float* __restrict__ bhf,
    const float* __restrict__ whb, const float* __restrict__ bhb,
    float* __restrict__ zout)
{
    const int b   = blockIdx.x & 63;
    const int dir = blockIdx.x >> 6;
    const float* gi  = dir ? gib : gif;
    const float* whh = dir ? whb : whf;
    const float* bhh = dir ? bhb : bhf;
    const int j = threadIdx.x;

    u64 w[64];
    {
        const u64* wp = (const u64*)(whh + j * 128);
#pragma unroll
        for (int k = 0; k < 64; k++) w[k] = wp[k];
    }
    const float bh = bhh[j];

    __shared__ __align__(16) float hsm[128];
    __shared__ float rsm[128];
    __shared__ float zsm[128];
    if (j < 128) hsm[j] = 0.0f;
    __syncthreads();

    const int step = dir ? -1 : 1;
    int tt = dir ? 1023 : 0;
    const float* gip = gi + (ll)b * (1024 * 384) + j;
    float* zrow = zout + (ll)b * (1024 * 256) + dir * 128;

    float gpre[4];
#pragma unroll
    for (int d = 0; d < 4; d++)
        gpre[d] = gip[((tt + d * step) & 1023) * 384];

    for (int t = 0; t < 1024; t += 4) {
#pragma unroll
        for (int u = 0; u < 4; u++) {
            float gcur = gpre[u];
            gpre[u] = gip[((tt + 4 * step) & 1023) * 384];

            u64 a0 = 0ULL, a1 = 0ULL, a2 = 0ULL, a3 = 0ULL;
            const ulonglong2* hp2 = (const ulonglong2*)hsm;
#pragma unroll
            for (int q = 0; q < 16; q++) {
                ulonglong2 u0 = hp2[2 * q];
                ulonglong2 u1 = hp2[2 * q + 1];
                a0 = ffma2(w[4 * q + 0], u0.x, a0);
                a1 = ffma2(w[4 * q + 1], u0.y, a1);
                a2 = ffma2(w[4 * q + 2], u1.x, a2);
                a3 = ffma2(w[4 * q + 3], u1.y, a3);
            }
            float2 f0 = unpack2(a0), f1 = unpack2(a1);
            float2 f2 = unpack2(a2), f3 = unpack2(a3);
            float gh = ((f0.x + f0.y) + (f1.x + f1.y)) +
                       ((f2.x + f2.y) + (f3.x + f3.y)) + bh;

            float hold = 0.0f;
            if (j >= 256) hold = hsm[j - 256];
            if (j < 128) {
                rsm[j] = sig_mufu(gcur + gh);
            } else if (j < 256) {
                zsm[j - 128] = sig_mufu(gcur + gh);
            }
            __syncthreads();
            if (j >= 256) {
                int i = j - 256;
                float n = tanh_mufu(fmaf(rsm[i], gh, gcur));
                float hnew = fmaf(zsm[i], hold - n, n);
                hsm[i] = hnew;
                zrow[tt * 256 + i] = hnew;
            }
            __syncthreads();
            tt += step;
        }
    }
}

// ---------------- attention pooling + heads ----------------
__global__ __launch_bounds__(256) void pool_heads(
    const float* __restrict__ z1,
    const float* __restrict__ attn_w, const float* __restrict__ attn_b,
    const float* __restrict__ motor_w, const float* __restrict__ motor_b,
    const float* __restrict__ state_w, const float* __restrict__ state_b,
    const int* __restrict__ motor_k,
    float* __restrict__ out)
{
    const int b = blockIdx.x;
    const int tid = threadIdx.x;
    const int lane = tid & 31;
    const int wrp = tid >> 5;

    __shared__ float aw[256];
    __shared__ float sc[1024];
    __shared__ float pl[256];
    __shared__ float red[40];

    aw[tid] = attn_w[tid];
    __syncthreads();

    const float* zb = z1 + (ll)b * 1024 * 256;

    for (int it = 0; it < 128; it++) {
        int t = it * 8 + wrp;
        const float* zr = zb + (ll)t * 256;
        float p = 0.0f;
#pragma unroll
        for (int q = 0; q < 8; q++)
            p = fmaf(zr[lane + 32 * q], aw[lane + 32 * q], p);
#pragma unroll
        for (int o = 16; o; o >>= 1) p += __shfl_down_sync(0xffffffffu, p, o);
        if (lane == 0) sc[t] = p + attn_b[0];
    }
    __syncthreads();

    float mx = -1e30f;
    for (int t = tid; t < 1024; t += 256) mx = fmaxf(mx, sc[t]);
#pragma unroll
    for (int o = 16; o; o >>= 1) mx = fmaxf(mx, __shfl_down_sync(0xffffffffu, mx, o));
    if (lane == 0) red[wrp] = mx;
    __syncthreads();
    if (tid == 0) {
        float m = red[0];
        for (int i = 1; i < 8; i++) m = fmaxf(m, red[i]);
        red[32] = m;
    }
    __syncthreads();
    mx = red[32];
    float s = 0.0f;
    for (int t = tid; t < 1024; t += 256) {
        float e = __expf(sc[t] - mx);
        sc[t] = e;
        s += e;
    }
#pragma unroll
    for (int o = 16; o; o >>= 1) s += __shfl_down_sync(0xffffffffu, s, o);
    if (lane == 0) red[wrp] = s;
    __syncthreads();
    if (tid == 0) {
        float m = 0.0f;
        for (int i = 0; i < 8; i++) m += red[i];
        red[33] = __fdividef(1.0f, m);
    }
    __syncthreads();
    const float inv = red[33];

    float ac0 = 0.0f, ac1 = 0.0f, ac2 = 0.0f, ac3 = 0.0f;
    for (int t = 0; t < 1024; t += 4) {
        ac0 = fmaf(sc[t + 0], zb[(ll)(t + 0) * 256 + tid], ac0);
        ac1 = fmaf(sc[t + 1], zb[(ll)(t + 1) * 256 + tid], ac1);
        ac2 = fmaf(sc[t + 2], zb[(ll)(t + 2) * 256 + tid], ac2);
        ac3 = fmaf(sc[t + 3], zb[(ll)(t + 3) * 256 + tid], ac3);
    }
    pl[tid] = ((ac0 + ac1) + (ac2 + ac3)) * inv;
    __syncthreads();

    if (wrp < 7) {
        const float* wv;
        float bias2;
        int k = motor_k[b];
        if (wrp < 5) {
            wv = motor_w + wrp * 256;
            bias2 = motor_b[wrp];
        } else {
            int c = wrp - 5;
            wv = state_w + (k * 2 + c) * 256;
            bias2 = state_b[k * 2 + c];
        }
        float p = 0.0f;
#pragma unroll
        for (int q = 0; q < 8; q++)
            p = fmaf(pl[lane + 32 * q], wv[lane + 32 * q], p);
#pragma unroll
        for (int o = 16; o; o >>= 1) p += __shfl_down_sync(0xffffffffu, p, o);
        if (lane == 0) {
            if (wrp < 5) out[b * 5 + wrp] = p + bias2;
            else         out[320 + b * 2 + (wrp - 5)] = p + bias2;
        }
    }
}

// ---------------- launcher ----------------
extern "C" void kernel_launch(void* const* d_in, const int* in_sizes, int n_in,
                              void* d_out, int out_size)
{
    const float* x        = (const float*)d_in[0];
    const int*   motor_k  = (const int*)d_in[1];
    const float* wih_l0f  = (const float*)d_in[2];
    const float* whh_l0f  = (const float*)d_in[3];
    const float* bih_l0f  = (const float*)d_in[4];
    const float* bhh_l0f  = (const float*)d_in[5];
    const float* wih_l0b  = (const float*)d_in[6];
    const float* whh_l0b  = (const float*)d_in[7];
    const float* bih_l0b  = (const float*)d_in[8];
    const float* bhh_l0b  = (const float*)d_in[9];
    const float* wih_l1f  = (const float*)d_in[10];
    const float* whh_l1f  = (const float*)d_in[11];
    const float* bih_l1f  = (const float*)d_in[12];
    const float* bhh_l1f  = (const float*)d_in[13];
    const float* wih_l1b  = (const float*)d_in[14];
    const float* whh_l1b  = (const float*)d_in[15];
    const float* bih_l1b  = (const float*)d_in[16];
    const float* bhh_l1b  = (const float*)d_in[17];
    const float* attn_w   = (const float*)d_in[18];
    const float* attn_b   = (const float*)d_in[19];
    const float* motor_w  = (const float*)d_in[20];
    const float* motor_b  = (const float*)d_in[21];
    const float* state_w  = (const float*)d_in[22];
    const float* state_b  = (const float*)d_in[23];

    float *gif, *gib, *z0, *z1;
    __nv_bfloat16 *ahi, *alo, *whiF, *wloF, *whiB, *wloB;
    cudaGetSymbolAddress((void**)&gif, g_gi_f);
    cudaGetSymbolAddress((void**)&gib, g_gi_b);
    cudaGetSymbolAddress((void**)&z0, g_z0);
    cudaGetSymbolAddress((void**)&z1, g_z1);
    cudaGetSymbolAddress((void**)&ahi, g_ahi);
    cudaGetSymbolAddress((void**)&alo, g_alo);
    cudaGetSymbolAddress((void**)&whiF, g_whi_f);
    cudaGetSymbolAddress((void**)&wloF, g_wlo_f);
    cudaGetSymbolAddress((void**)&whiB, g_whi_b);
    cudaGetSymbolAddress((void**)&wloB, g_wlo_b);

    dim3 gg(3, 512, 2);   // n-tiles, m-tiles, dirs

    // ---- layer 0 (K=64) ----
    split_bf16<<<4096, 256>>>(x, ahi, alo, 65536 * 64 / 4);
    split_bf16<<<24, 256>>>(wih_l0f, whiF, wloF, 384 * 64 / 4);
    split_bf16<<<24, 256>>>(wih_l0b, whiB, wloB, 384 * 64 / 4);
    mma_gemm<<<gg, 256>>>(ahi, alo, whiF, wloF, whiB, wloB,
                          bih_l0f, bih_l0b, gif, gib, 64);
    gru_scan<<<128, 384>>>(gif, gib, whh_l0f, bhh_l0f, whh_l0b, bhh_l0b, z0);

    // ---- layer 1 (K=256) ----
    split_bf16<<<16384, 256>>>(z0, ahi, alo, 65536 * 256 / 4);
    split_bf16<<<96, 256>>>(wih_l1f, whiF, wloF, 384 * 256 / 4);
    split_bf16<<<96, 256>>>(wih_l1b, whiB, wloB, 384 * 256 / 4);
    mma_gemm<<<gg, 256>>>(ahi, alo, whiF, wloF, whiB, wloB,
                          bih_l1f, bih_l1b, gif, gib, 256);
    gru_scan<<<128, 384>>>(gif, gib, whh_l1f, bhh_l1f, whh_l1b, bhh_l1b, z1);

    // ---- pooling + heads ----
    pool_heads<<<64, 256>>>(z1, attn_w, attn_b, motor_w, motor_b,
                            state_w, state_b, motor_k, (float*)d_out);
}

// round 11
// speedup vs baseline: 1.6507x; 1.0207x over previous
#include <cuda_runtime.h>
#include <cuda_bf16.h>

typedef unsigned long long u64;
typedef long long ll;
typedef unsigned int u32;

// ---------------- scratch (no allocations allowed) ----------------
__device__ float g_gi_f[64 * 1024 * 384];
__device__ float g_gi_b[64 * 1024 * 384];
__device__ float g_z0[64 * 1024 * 256];
__device__ float g_z1[64 * 1024 * 256];
__device__ __nv_bfloat16 g_ahi[64 * 1024 * 256];
__device__ __nv_bfloat16 g_alo[64 * 1024 * 256];
__device__ __nv_bfloat16 g_whi_f[384 * 256];
__device__ __nv_bfloat16 g_wlo_f[384 * 256];
__device__ __nv_bfloat16 g_whi_b[384 * 256];
__device__ __nv_bfloat16 g_wlo_b[384 * 256];

// ---------------- f32x2 helpers ----------------
__device__ __forceinline__ u64 ffma2(u64 a, u64 b, u64 c) {
    u64 d;
    asm("fma.rn.f32x2 %0, %1, %2, %3;" : "=l"(d) : "l"(a), "l"(b), "l"(c));
    return d;
}
__device__ __forceinline__ float2 unpack2(u64 v) {
    float2 f;
    asm("mov.b64 {%0, %1}, %2;" : "=f"(f.x), "=f"(f.y) : "l"(v));
    return f;
}
__device__ __forceinline__ float tanh_mufu(float x) {
    float y;
    asm("tanh.approx.f32 %0, %1;" : "=f"(y) : "f"(x));
    return y;
}
__device__ __forceinline__ float sig_mufu(float x) {
    return fmaf(0.5f, tanh_mufu(0.5f * x), 0.5f);
}

// ---------------- mma.sync helpers (base ISA, works on compute_103) --------
__device__ __forceinline__ u32 smem_u32(const void* p) {
    u32 a;
    asm("{ .reg .u64 t; cvta.to.shared.u64 t, %1; cvt.u32.u64 %0, t; }"
        : "=r"(a) : "l"(p));
    return a;
}
__device__ __forceinline__ void ldsm_x4(u32* r, u32 addr) {
    asm volatile("ldmatrix.sync.aligned.m8n8.x4.shared.b16 {%0,%1,%2,%3}, [%4];"
                 : "=r"(r[0]), "=r"(r[1]), "=r"(r[2]), "=r"(r[3]) : "r"(addr));
}
__device__ __forceinline__ void ldsm_x2(u32* r, u32 addr) {
    asm volatile("ldmatrix.sync.aligned.m8n8.x2.shared.b16 {%0,%1}, [%2];"
                 : "=r"(r[0]), "=r"(r[1]) : "r"(addr));
}
__device__ __forceinline__ void mma16816(float* c, const u32* a, const u32* b) {
    asm volatile(
        "mma.sync.aligned.m16n8k16.row.col.f32.bf16.bf16.f32 "
        "{%0,%1,%2,%3}, {%4,%5,%6,%7}, {%8,%9}, {%0,%1,%2,%3};"
        : "+f"(c[0]), "+f"(c[1]), "+f"(c[2]), "+f"(c[3])
        : "r"(a[0]), "r"(a[1]), "r"(a[2]), "r"(a[3]), "r"(b[0]), "r"(b[1]));
}

// ---------------- bf16 hi/lo split conversion ----------------
__global__ void split_bf16(const float* __restrict__ a,
                           __nv_bfloat16* __restrict__ hi,
                           __nv_bfloat16* __restrict__ lo, int n4)
{
    int i = blockIdx.x * blockDim.x + threadIdx.x;
    if (i >= n4) return;
    float4 v = ((const float4*)a)[i];
    __nv_bfloat16 h0 = __float2bfloat16(v.x);
    __nv_bfloat16 h1 = __float2bfloat16(v.y);
    __nv_bfloat16 h2 = __float2bfloat16(v.z);
    __nv_bfloat16 h3 = __float2bfloat16(v.w);
    __nv_bfloat16 l0 = __float2bfloat16(v.x - __bfloat162float(h0));
    __nv_bfloat16 l1 = __float2bfloat16(v.y - __bfloat162float(h1));
    __nv_bfloat16 l2 = __float2bfloat16(v.z - __bfloat162float(h2));
    __nv_bfloat16 l3 = __float2bfloat16(v.w - __bfloat162float(h3));
    ((__nv_bfloat162*)hi)[2 * i]     = __nv_bfloat162(h0, h1);
    ((__nv_bfloat162*)hi)[2 * i + 1] = __nv_bfloat162(h2, h3);
    ((__nv_bfloat162*)lo)[2 * i]     = __nv_bfloat162(l0, l1);
    ((__nv_bfloat162*)lo)[2 * i + 1] = __nv_bfloat162(l2, l3);
}

// ---------------- tensor-core GEMM via mma.sync (R9-proven) ----------------
static constexpr int LDS = 40;

__global__ void __launch_bounds__(256, 1) mma_gemm(
    const __nv_bfloat16* __restrict__ ahi, const __nv_bfloat16* __restrict__ alo,
    const __nv_bfloat16* __restrict__ whif, const __nv_bfloat16* __restrict__ wlof,
    const __nv_bfloat16* __restrict__ whib, const __nv_bfloat16* __restrict__ wlob,
    const float* __restrict__ biasf, const float* __restrict__ biasb,
    float* __restrict__ cf, float* __restrict__ cb, int K)
{
    const int dir = blockIdx.z;
    const __nv_bfloat16* whi = dir ? whib : whif;
    const __nv_bfloat16* wlo = dir ? wlob : wlof;
    const float* bias = dir ? biasb : biasf;
    float* C = dir ? cb : cf;

    const int nBase = blockIdx.x * 128;
    const int mBase = blockIdx.y * 128;
    const int tid = threadIdx.x;
    const int lane = tid & 31;
    const int warp = tid >> 5;
    const int mw = (warp & 1) * 64;
    const int nw = (warp >> 1) * 32;

    __shared__ __nv_bfloat16 sAhi[128 * LDS];
    __shared__ __nv_bfloat16 sAlo[128 * LDS];
    __shared__ __nv_bfloat16 sWhi[128 * LDS];
    __shared__ __nv_bfloat16 sWlo[128 * LDS];

    float acc[4][4][4];
#pragma unroll
    for (int i = 0; i < 4; i++)
#pragma unroll
        for (int j = 0; j < 4; j++)
#pragma unroll
            for (int r = 0; r < 4; r++) acc[i][j][r] = 0.0f;

    const u32 bAhi = smem_u32(sAhi), bAlo = smem_u32(sAlo);
    const u32 bWhi = smem_u32(sWhi), bWlo = smem_u32(sWlo);

    const u32 a_row = mw + (lane & 15);
    const u32 a_col = (lane >> 4) * 8;
    const u32 b_row = nw + (lane & 7);
    const u32 b_col = ((lane >> 3) & 1) * 8;

    const int nChunks = K >> 5;
    for (int c = 0; c < nChunks; c++) {
        const int kc = c << 5;
        __syncthreads();
#pragma unroll
        for (int it = 0; it < 4; it++) {
            int u = it * 256 + tid;
            int row = u >> 3, seg = u & 7;
            u32 so = (u32)(row * LDS + seg * 4);
            ll asrc = (ll)(mBase + row) * K + kc + seg * 4;
            ll wsrc = (ll)(nBase + row) * K + kc + seg * 4;
            *(u64*)(sAhi + so) = *(const u64*)(ahi + asrc);
            *(u64*)(sAlo + so) = *(const u64*)(alo + asrc);
            *(u64*)(sWhi + so) = *(const u64*)(whi + wsrc);
            *(u64*)(sWlo + so) = *(const u64*)(wlo + wsrc);
        }
        __syncthreads();

#pragma unroll
        for (int ks = 0; ks < 2; ks++) {
            const u32 k16 = ks * 16;
            u32 fahi[4][4], falo[4][4];
#pragma unroll
            for (int ms = 0; ms < 4; ms++) {
                u32 off = ((a_row + ms * 16) * LDS + a_col + k16) * 2;
                ldsm_x4(fahi[ms], bAhi + off);
                ldsm_x4(falo[ms], bAlo + off);
            }
            u32 fbhi[4][2], fblo[4][2];
#pragma unroll
            for (int ns = 0; ns < 4; ns++) {
                u32 off = ((b_row + ns * 8) * LDS + b_col + k16) * 2;
                ldsm_x2(fbhi[ns], bWhi + off);
                ldsm_x2(fblo[ns], bWlo + off);
            }
#pragma unroll
            for (int ms = 0; ms < 4; ms++)
#pragma unroll
                for (int ns = 0; ns < 4; ns++) {
                    mma16816(acc[ms][ns], fahi[ms], fbhi[ns]);
                    mma16816(acc[ms][ns], fahi[ms], fblo[ns]);
                    mma16816(acc[ms][ns], falo[ms], fbhi[ns]);
                }
        }
    }

    const int cbase = nBase + nw + 2 * (lane & 3);
    float2 bv[4];
#pragma unroll
    for (int ns = 0; ns < 4; ns++) {
        bv[ns].x = __ldg(&bias[cbase + ns * 8]);
        bv[ns].y = __ldg(&bias[cbase + ns * 8 + 1]);
    }
#pragma unroll
    for (int ms = 0; ms < 4; ms++) {
        int r0 = mBase + mw + ms * 16 + (lane >> 2);
#pragma unroll
        for (int ns = 0; ns < 4; ns++) {
            int col = cbase + ns * 8;
            float2 lo2, hi2;
            lo2.x = acc[ms][ns][0] + bv[ns].x;
            lo2.y = acc[ms][ns][1] + bv[ns].y;
            hi2.x = acc[ms][ns][2] + bv[ns].x;
            hi2.y = acc[ms][ns][3] + bv[ns].y;
            *(float2*)(C + (ll)r0 * 384 + col)       = lo2;
            *(float2*)(C + (ll)(r0 + 8) * 384 + col) = hi2;
        }
    }
}

// ---------------- GRU scan: quad-per-row, 1 barrier/step ----------------
// 512 threads = 128 quads. Quad i owns row i. Lane g owns h-segment
// [32g,32g+32) and computes r/z/n partial dots (48 FFMA2). Intra-quad
// shfl.xor reduction -> all lanes hold full sums; gates computed redundantly;
// lane 0 publishes h to ping-pong hsm (skewed 36-float segment stride to
// avoid bank conflicts). gi prefetch distance 4 (R6-proven).
__global__ __launch_bounds__(512, 1) void gru_scan(
    const float* __restrict__ gif, const float* __restrict__ gib,
    const float* __restrict__ whf, const float* __restrict__ bhf,
    const float* __restrict__ whb, const float* __restrict__ bhb,
    float* __restrict__ zout)
{
    const int b   = blockIdx.x & 63;
    const int dir = blockIdx.x >> 6;
    const float* gi  = dir ? gib : gif;
    const float* whh = dir ? whb : whf;
    const float* bhh = dir ? bhb : bhf;

    const int tid = threadIdx.x;
    const int i = tid >> 2;                 // row 0..127
    const int g = tid & 3;                  // k-segment 0..3
    const int laneBase = (tid & 31) & ~3;   // quad base lane in warp

    // weights: rows i (r), i+128 (z), i+256 (n); cols [32g, 32g+32)
    u64 wr[16], wz[16], wn[16];
    {
        const u64* pr = (const u64*)(whh + (i      ) * 128 + g * 32);
        const u64* pz = (const u64*)(whh + (i + 128) * 128 + g * 32);
        const u64* pn = (const u64*)(whh + (i + 256) * 128 + g * 32);
#pragma unroll
        for (int k = 0; k < 16; k++) { wr[k] = pr[k]; wz[k] = pz[k]; wn[k] = pn[k]; }
    }
    const float br = bhh[i], bz = bhh[i + 128], bn = bhh[i + 256];

    // ping-pong h buffers, segment-skewed: segment s at floats [36s, 36s+32)
    __shared__ __align__(16) float hsm[2][144];
    if (tid < 144) hsm[0][tid] = 0.0f;
    __syncthreads();

    const int step = dir ? -1 : 1;
    int tt = dir ? 1023 : 0;
    const int grow = i + 128 * ((g == 3) ? 0 : g);   // lane 3 duplicates gate r
    const float* gip = gi + (ll)b * (1024 * 384) + grow;
    float* zrow = zout + (ll)b * (1024 * 256) + dir * 128 + i;
    const int hsl = ((i >> 5) * 36) + (i & 31);      // skewed slot of row i

    float gpre[4];
#pragma unroll
    for (int d = 0; d < 4; d++)
        gpre[d] = gip[((tt + d * step) & 1023) * 384];

    float hprev = 0.0f;
    int buf = 0;

    for (int t = 0; t < 1024; t += 4) {
#pragma unroll
        for (int u = 0; u < 4; u++) {
            float gcur = gpre[u];
            gpre[u] = gip[((tt + 4 * step) & 1023) * 384];

            // partial dots over this lane's 32-float h segment
            const ulonglong2* hp2 = (const ulonglong2*)(&hsm[buf][g * 36]);
            u64 ar = 0ULL, az = 0ULL, an = 0ULL;
#pragma unroll
            for (int q = 0; q < 8; q++) {
                ulonglong2 hv = hp2[q];
                ar = ffma2(wr[2 * q], hv.x, ar);
                ar = ffma2(wr[2 * q + 1], hv.y, ar);
                az = ffma2(wz[2 * q], hv.x, az);
                az = ffma2(wz[2 * q + 1], hv.y, az);
                an = ffma2(wn[2 * q], hv.x, an);
                an = ffma2(wn[2 * q + 1], hv.y, an);
            }
            float2 fr = unpack2(ar), fz = unpack2(az), fn = unpack2(an);
            float sr = fr.x + fr.y, sz = fz.x + fz.y, sn = fn.x + fn.y;
            // intra-quad butterfly: all 4 lanes end with full sums
            sr += __shfl_xor_sync(0xffffffffu, sr, 1);
            sr += __shfl_xor_sync(0xffffffffu, sr, 2);
            sz += __shfl_xor_sync(0xffffffffu, sz, 1);
            sz += __shfl_xor_sync(0xffffffffu, sz, 2);
            sn += __shfl_xor_sync(0xffffffffu, sn, 1);
            sn += __shfl_xor_sync(0xffffffffu, sn, 2);
            // gather the three gi values from quad lanes 0/1/2
            float gr = __shfl_sync(0xffffffffu, gcur, laneBase + 0);
            float gz = __shfl_sync(0xffffffffu, gcur, laneBase + 1);
            float gn = __shfl_sync(0xffffffffu, gcur, laneBase + 2);
            // gates (computed redundantly by all 4 lanes -> identical)
            float r  = sig_mufu(gr + sr + br);
            float zv = sig_mufu(gz + sz + bz);
            float n  = tanh_mufu(fmaf(r, sn + bn, gn));
            float hnew = fmaf(zv, hprev - n, n);   // (1-z)n + z h
            hprev = hnew;
            if (g == 0) {
                hsm[buf ^ 1][hsl] = hnew;          // write OTHER buffer: no race
                zrow[tt * 256] = hnew;
            }
            __syncthreads();                       // publish h for next step
            buf ^= 1;
            tt += step;
        }
    }
}

// ---------------- attention pooling + heads ----------------
__global__ __launch_bounds__(256) void pool_heads(
    const float* __restrict__ z1,
    const float* __restrict__ attn_w, const float* __restrict__ attn_b,
    const float* __restrict__ motor_w, const float* __restrict__ motor_b,
    const float* __restrict__ state_w, const float* __restrict__ state_b,
    const int* __restrict__ motor_k,
    float* __restrict__ out)
{
    const int b = blockIdx.x;
    const int tid = threadIdx.x;
    const int lane = tid & 31;
    const int wrp = tid >> 5;

    __shared__ float aw[256];
    __shared__ float sc[1024];
    __shared__ float pl[256];
    __shared__ float red[40];

    aw[tid] = attn_w[tid];
    __syncthreads();

    const float* zb = z1 + (ll)b * 1024 * 256;

    for (int it = 0; it < 128; it++) {
        int t = it * 8 + wrp;
        const float* zr = zb + (ll)t * 256;
        float p = 0.0f;
#pragma unroll
        for (int q = 0; q < 8; q++)
            p = fmaf(zr[lane + 32 * q], aw[lane + 32 * q], p);
#pragma unroll
        for (int o = 16; o; o >>= 1) p += __shfl_down_sync(0xffffffffu, p, o);
        if (lane == 0) sc[t] = p + attn_b[0];
    }
    __syncthreads();

    float mx = -1e30f;
    for (int t = tid; t < 1024; t += 256) mx = fmaxf(mx, sc[t]);
#pragma unroll
    for (int o = 16; o; o >>= 1) mx = fmaxf(mx, __shfl_down_sync(0xffffffffu, mx, o));
    if (lane == 0) red[wrp] = mx;
    __syncthreads();
    if (tid == 0) {
        float m = red[0];
        for (int i = 1; i < 8; i++) m = fmaxf(m, red[i]);
        red[32] = m;
    }
    __syncthreads();
    mx = red[32];
    float s = 0.0f;
    for (int t = tid; t < 1024; t += 256) {
        float e = __expf(sc[t] - mx);
        sc[t] = e;
        s += e;
    }
#pragma unroll
    for (int o = 16; o; o >>= 1) s += __shfl_down_sync(0xffffffffu, s, o);
    if (lane == 0) red[wrp] = s;
    __syncthreads();
    if (tid == 0) {
        float m = 0.0f;
        for (int i = 0; i < 8; i++) m += red[i];
        red[33] = __fdividef(1.0f, m);
    }
    __syncthreads();
    const float inv = red[33];

    float ac0 = 0.0f, ac1 = 0.0f, ac2 = 0.0f, ac3 = 0.0f;
    for (int t = 0; t < 1024; t += 4) {
        ac0 = fmaf(sc[t + 0], zb[(ll)(t + 0) * 256 + tid], ac0);
        ac1 = fmaf(sc[t + 1], zb[(ll)(t + 1) * 256 + tid], ac1);
        ac2 = fmaf(sc[t + 2], zb[(ll)(t + 2) * 256 + tid], ac2);
        ac3 = fmaf(sc[t + 3], zb[(ll)(t + 3) * 256 + tid], ac3);
    }
    pl[tid] = ((ac0 + ac1) + (ac2 + ac3)) * inv;
    __syncthreads();

    if (wrp < 7) {
        const float* wv;
        float bias2;
        int k = motor_k[b];
        if (wrp < 5) {
            wv = motor_w + wrp * 256;
            bias2 = motor_b[wrp];
        } else {
            int c = wrp - 5;
            wv = state_w + (k * 2 + c) * 256;
            bias2 = state_b[k * 2 + c];
        }
        float p = 0.0f;
#pragma unroll
        for (int q = 0; q < 8; q++)
            p = fmaf(pl[lane + 32 * q], wv[lane + 32 * q], p);
#pragma unroll
        for (int o = 16; o; o >>= 1) p += __shfl_down_sync(0xffffffffu, p, o);
        if (lane == 0) {
            if (wrp < 5) out[b * 5 + wrp] = p + bias2;
            else         out[320 + b * 2 + (wrp - 5)] = p + bias2;
        }
    }
}

// ---------------- launcher ----------------
extern "C" void kernel_launch(void* const* d_in, const int* in_sizes, int n_in,
                              void* d_out, int out_size)
{
    const float* x        = (const float*)d_in[0];
    const int*   motor_k  = (const int*)d_in[1];
    const float* wih_l0f  = (const float*)d_in[2];
    const float* whh_l0f  = (const float*)d_in[3];
    const float* bih_l0f  = (const float*)d_in[4];
    const float* bhh_l0f  = (const float*)d_in[5];
    const float* wih_l0b  = (const float*)d_in[6];
    const float* whh_l0b  = (const float*)d_in[7];
    const float* bih_l0b  = (const float*)d_in[8];
    const float* bhh_l0b  = (const float*)d_in[9];
    const float* wih_l1f  = (const float*)d_in[10];
    const float* whh_l1f  = (const float*)d_in[11];
    const float* bih_l1f  = (const float*)d_in[12];
    const float* bhh_l1f  = (const float*)d_in[13];
    const float* wih_l1b  = (const float*)d_in[14];
    const float* whh_l1b  = (const float*)d_in[15];
    const float* bih_l1b  = (const float*)d_in[16];
    const float* bhh_l1b  = (const float*)d_in[17];
    const float* attn_w   = (const float*)d_in[18];
    const float* attn_b   = (const float*)d_in[19];
    const float* motor_w  = (const float*)d_in[20];
    const float* motor_b  = (const float*)d_in[21];
    const float* state_w  = (const float*)d_in[22];
    const float* state_b  = (const float*)d_in[23];

    float *gif, *gib, *z0, *z1;
    __nv_bfloat16 *ahi, *alo, *whiF, *wloF, *whiB, *wloB;
    cudaGetSymbolAddress((void**)&gif, g_gi_f);
    cudaGetSymbolAddress((void**)&gib, g_gi_b);
    cudaGetSymbolAddress((void**)&z0, g_z0);
    cudaGetSymbolAddress((void**)&z1, g_z1);
    cudaGetSymbolAddress((void**)&ahi, g_ahi);
    cudaGetSymbolAddress((void**)&alo, g_alo);
    cudaGetSymbolAddress((void**)&whiF, g_whi_f);
    cudaGetSymbolAddress((void**)&wloF, g_wlo_f);
    cudaGetSymbolAddress((void**)&whiB, g_whi_b);
    cudaGetSymbolAddress((void**)&wloB, g_wlo_b);

    dim3 gg(3, 512, 2);   // n-tiles, m-tiles, dirs

    // ---- layer 0 (K=64) ----
    split_bf16<<<4096, 256>>>(x, ahi, alo, 65536 * 64 / 4);
    split_bf16<<<24, 256>>>(wih_l0f, whiF, wloF, 384 * 64 / 4);
    split_bf16<<<24, 256>>>(wih_l0b, whiB, wloB, 384 * 64 / 4);
    mma_gemm<<<gg, 256>>>(ahi, alo, whiF, wloF, whiB, wloB,
                          bih_l0f, bih_l0b, gif, gib, 64);
    gru_scan<<<128, 512>>>(gif, gib, whh_l0f, bhh_l0f, whh_l0b, bhh_l0b, z0);

    // ---- layer 1 (K=256) ----
    split_bf16<<<16384, 256>>>(z0, ahi, alo, 65536 * 256 / 4);
    split_bf16<<<96, 256>>>(wih_l1f, whiF, wloF, 384 * 256 / 4);
    split_bf16<<<96, 256>>>(wih_l1b, whiB, wloB, 384 * 256 / 4);
    mma_gemm<<<gg, 256>>>(ahi, alo, whiF, wloF, whiB, wloB,
                          bih_l1f, bih_l1b, gif, gib, 256);
    gru_scan<<<128, 512>>>(gif, gib, whh_l1f, bhh_l1f, whh_l1b, bhh_l1b, z1);

    // ---- pooling + heads ----
    pool_heads<<<64, 256>>>(z1, attn_w, attn_b, motor_w, motor_b,
                            state_w, state_b, motor_k, (float*)d_out);
}

// round 13
// speedup vs baseline: 1.8420x; 1.1159x over previous
#include <cuda_runtime.h>
#include <cuda_bf16.h>

typedef unsigned long long u64;
typedef long long ll;
typedef unsigned int u32;

// ---------------- scratch (no allocations allowed) ----------------
__device__ float g_gi_f[64 * 1024 * 384];
__device__ float g_gi_b[64 * 1024 * 384];
__device__ float g_z1[64 * 1024 * 256];
__device__ __nv_bfloat16 g_ahi[64 * 1024 * 256];
__device__ __nv_bfloat16 g_alo[64 * 1024 * 256];
__device__ __nv_bfloat16 g_whi_f[384 * 256];
__device__ __nv_bfloat16 g_wlo_f[384 * 256];
__device__ __nv_bfloat16 g_whi_b[384 * 256];
__device__ __nv_bfloat16 g_wlo_b[384 * 256];
__device__ float g_attn[64 * 1024];
__device__ float g_part[64 * 16 * 256];

// ---------------- f32x2 helpers ----------------
__device__ __forceinline__ u64 ffma2(u64 a, u64 b, u64 c) {
    u64 d;
    asm("fma.rn.f32x2 %0, %1, %2, %3;" : "=l"(d) : "l"(a), "l"(b), "l"(c));
    return d;
}
__device__ __forceinline__ float2 unpack2(u64 v) {
    float2 f;
    asm("mov.b64 {%0, %1}, %2;" : "=f"(f.x), "=f"(f.y) : "l"(v));
    return f;
}
__device__ __forceinline__ float tanh_mufu(float x) {
    float y;
    asm("tanh.approx.f32 %0, %1;" : "=f"(y) : "f"(x));
    return y;
}
__device__ __forceinline__ float sig_mufu(float x) {
    return fmaf(0.5f, tanh_mufu(0.5f * x), 0.5f);
}

// ---------------- mma.sync helpers ----------------
__device__ __forceinline__ u32 smem_u32(const void* p) {
    u32 a;
    asm("{ .reg .u64 t; cvta.to.shared.u64 t, %1; cvt.u32.u64 %0, t; }"
        : "=r"(a) : "l"(p));
    return a;
}
__device__ __forceinline__ void ldsm_x4(u32* r, u32 addr) {
    asm volatile("ldmatrix.sync.aligned.m8n8.x4.shared.b16 {%0,%1,%2,%3}, [%4];"
                 : "=r"(r[0]), "=r"(r[1]), "=r"(r[2]), "=r"(r[3]) : "r"(addr));
}
__device__ __forceinline__ void ldsm_x2(u32* r, u32 addr) {
    asm volatile("ldmatrix.sync.aligned.m8n8.x2.shared.b16 {%0,%1}, [%2];"
                 : "=r"(r[0]), "=r"(r[1]) : "r"(addr));
}
__device__ __forceinline__ void mma16816(float* c, const u32* a, const u32* b) {
    asm volatile(
        "mma.sync.aligned.m16n8k16.row.col.f32.bf16.bf16.f32 "
        "{%0,%1,%2,%3}, {%4,%5,%6,%7}, {%8,%9}, {%0,%1,%2,%3};"
        : "+f"(c[0]), "+f"(c[1]), "+f"(c[2]), "+f"(c[3])
        : "r"(a[0]), "r"(a[1]), "r"(a[2]), "r"(a[3]), "r"(b[0]), "r"(b[1]));
}

// ---------------- bf16 hi/lo split conversion ----------------
__global__ void split_bf16(const float* __restrict__ a,
                           __nv_bfloat16* __restrict__ hi,
                           __nv_bfloat16* __restrict__ lo, int n4)
{
    int i = blockIdx.x * blockDim.x + threadIdx.x;
    if (i >= n4) return;
    float4 v = ((const float4*)a)[i];
    __nv_bfloat16 h0 = __float2bfloat16(v.x);
    __nv_bfloat16 h1 = __float2bfloat16(v.y);
    __nv_bfloat16 h2 = __float2bfloat16(v.z);
    __nv_bfloat16 h3 = __float2bfloat16(v.w);
    __nv_bfloat16 l0 = __float2bfloat16(v.x - __bfloat162float(h0));
    __nv_bfloat16 l1 = __float2bfloat16(v.y - __bfloat162float(h1));
    __nv_bfloat16 l2 = __float2bfloat16(v.z - __bfloat162float(h2));
    __nv_bfloat16 l3 = __float2bfloat16(v.w - __bfloat162float(h3));
    ((__nv_bfloat162*)hi)[2 * i]     = __nv_bfloat162(h0, h1);
    ((__nv_bfloat162*)hi)[2 * i + 1] = __nv_bfloat162(h2, h3);
    ((__nv_bfloat162*)lo)[2 * i]     = __nv_bfloat162(l0, l1);
    ((__nv_bfloat162*)lo)[2 * i + 1] = __nv_bfloat162(l2, l3);
}

// ---------------- tensor-core GEMM via mma.sync (R9-proven) ----------------
static constexpr int LDS = 40;

__global__ void __launch_bounds__(256, 1) mma_gemm(
    const __nv_bfloat16* __restrict__ ahi, const __nv_bfloat16* __restrict__ alo,
    const __nv_bfloat16* __restrict__ whif, const __nv_bfloat16* __restrict__ wlof,
    const __nv_bfloat16* __restrict__ whib, const __nv_bfloat16* __restrict__ wlob,
    const float* __restrict__ biasf, const float* __restrict__ biasb,
    float* __restrict__ cf, float* __restrict__ cb, int K)
{
    const int dir = blockIdx.z;
    const __nv_bfloat16* whi = dir ? whib : whif;
    const __nv_bfloat16* wlo = dir ? wlob : wlof;
    const float* bias = dir ? biasb : biasf;
    float* C = dir ? cb : cf;

    const int nBase = blockIdx.x * 128;
    const int mBase = blockIdx.y * 128;
    const int tid = threadIdx.x;
    const int lane = tid & 31;
    const int warp = tid >> 5;
    const int mw = (warp & 1) * 64;
    const int nw = (warp >> 1) * 32;

    __shared__ __nv_bfloat16 sAhi[128 * LDS];
    __shared__ __nv_bfloat16 sAlo[128 * LDS];
    __shared__ __nv_bfloat16 sWhi[128 * LDS];
    __shared__ __nv_bfloat16 sWlo[128 * LDS];

    float acc[4][4][4];
#pragma unroll
    for (int i = 0; i < 4; i++)
#pragma unroll
        for (int j = 0; j < 4; j++)
#pragma unroll
            for (int r = 0; r < 4; r++) acc[i][j][r] = 0.0f;

    const u32 bAhi = smem_u32(sAhi), bAlo = smem_u32(sAlo);
    const u32 bWhi = smem_u32(sWhi), bWlo = smem_u32(sWlo);

    const u32 a_row = mw + (lane & 15);
    const u32 a_col = (lane >> 4) * 8;
    const u32 b_row = nw + (lane & 7);
    const u32 b_col = ((lane >> 3) & 1) * 8;

    const int nChunks = K >> 5;
    for (int c = 0; c < nChunks; c++) {
        const int kc = c << 5;
        __syncthreads();
#pragma unroll
        for (int it = 0; it < 4; it++) {
            int u = it * 256 + tid;
            int row = u >> 3, seg = u & 7;
            u32 so = (u32)(row * LDS + seg * 4);
            ll asrc = (ll)(mBase + row) * K + kc + seg * 4;
            ll wsrc = (ll)(nBase + row) * K + kc + seg * 4;
            *(u64*)(sAhi + so) = *(const u64*)(ahi + asrc);
            *(u64*)(sAlo + so) = *(const u64*)(alo + asrc);
            *(u64*)(sWhi + so) = *(const u64*)(whi + wsrc);
            *(u64*)(sWlo + so) = *(const u64*)(wlo + wsrc);
        }
        __syncthreads();

#pragma unroll
        for (int ks = 0; ks < 2; ks++) {
            const u32 k16 = ks * 16;
            u32 fahi[4][4], falo[4][4];
#pragma unroll
            for (int ms = 0; ms < 4; ms++) {
                u32 off = ((a_row + ms * 16) * LDS + a_col + k16) * 2;
                ldsm_x4(fahi[ms], bAhi + off);
                ldsm_x4(falo[ms], bAlo + off);
            }
            u32 fbhi[4][2], fblo[4][2];
#pragma unroll
            for (int ns = 0; ns < 4; ns++) {
                u32 off = ((b_row + ns * 8) * LDS + b_col + k16) * 2;
                ldsm_x2(fbhi[ns], bWhi + off);
                ldsm_x2(fblo[ns], bWlo + off);
            }
#pragma unroll
            for (int ms = 0; ms < 4; ms++)
#pragma unroll
                for (int ns = 0; ns < 4; ns++) {
                    mma16816(acc[ms][ns], fahi[ms], fbhi[ns]);
                    mma16816(acc[ms][ns], fahi[ms], fblo[ns]);
                    mma16816(acc[ms][ns], falo[ms], fbhi[ns]);
                }
        }
    }

    const int cbase = nBase + nw + 2 * (lane & 3);
    float2 bv[4];
#pragma unroll
    for (int ns = 0; ns < 4; ns++) {
        bv[ns].x = __ldg(&bias[cbase + ns * 8]);
        bv[ns].y = __ldg(&bias[cbase + ns * 8 + 1]);
    }
#pragma unroll
    for (int ms = 0; ms < 4; ms++) {
        int r0 = mBase + mw + ms * 16 + (lane >> 2);
#pragma unroll
        for (int ns = 0; ns < 4; ns++) {
            int col = cbase + ns * 8;
            float2 lo2, hi2;
            lo2.x = acc[ms][ns][0] + bv[ns].x;
            lo2.y = acc[ms][ns][1] + bv[ns].y;
            hi2.x = acc[ms][ns][2] + bv[ns].x;
            hi2.y = acc[ms][ns][3] + bv[ns].y;
            *(float2*)(C + (ll)r0 * 384 + col)       = lo2;
            *(float2*)(C + (ll)(r0 + 8) * 384 + col) = hi2;
        }
    }
}

// ---------------- GRU scan: quad-per-row (R11-proven core) ----------------
// wbf=1: write h directly as bf16 hi/lo pair (feeds next layer's mma_gemm).
// wbf=0: write float z (for pooling).
__global__ __launch_bounds__(512, 1) void gru_scan(
    const float* __restrict__ gif, const float* __restrict__ gib,
    const float* __restrict__ whf, const float* __restrict__ bhf,
    const float* __restrict__ whb, const float* __restrict__ bhb,
    float* __restrict__ outf,
    __nv_bfloat16* __restrict__ ohi, __nv_bfloat16* __restrict__ olo,
    int wbf)
{
    const int b   = blockIdx.x & 63;
    const int dir = blockIdx.x >> 6;
    const float* gi  = dir ? gib : gif;
    const float* whh = dir ? whb : whf;
    const float* bhh = dir ? bhb : bhf;

    const int tid = threadIdx.x;
    const int i = tid >> 2;
    const int g = tid & 3;
    const int laneBase = (tid & 31) & ~3;

    u64 wr[16], wz[16], wn[16];
    {
        const u64* pr = (const u64*)(whh + (i      ) * 128 + g * 32);
        const u64* pz = (const u64*)(whh + (i + 128) * 128 + g * 32);
        const u64* pn = (const u64*)(whh + (i + 256) * 128 + g * 32);
#pragma unroll
        for (int k = 0; k < 16; k++) { wr[k] = pr[k]; wz[k] = pz[k]; wn[k] = pn[k]; }
    }
    const float br = bhh[i], bz = bhh[i + 128], bn = bhh[i + 256];

    __shared__ __align__(16) float hsm[2][144];
    if (tid < 144) hsm[0][tid] = 0.0f;
    __syncthreads();

    const int step = dir ? -1 : 1;
    int tt = dir ? 1023 : 0;
    const int grow = i + 128 * ((g == 3) ? 0 : g);
    const float* gip = gi + (ll)b * (1024 * 384) + grow;
    const ll obase = (ll)b * (1024 * 256) + dir * 128 + i;
    const int hsl = ((i >> 5) * 36) + (i & 31);

    float gpre[4];
#pragma unroll
    for (int d = 0; d < 4; d++)
        gpre[d] = gip[((tt + d * step) & 1023) * 384];

    float hprev = 0.0f;
    int buf = 0;

    for (int t = 0; t < 1024; t += 4) {
#pragma unroll
        for (int u = 0; u < 4; u++) {
            float gcur = gpre[u];
            gpre[u] = gip[((tt + 4 * step) & 1023) * 384];

            const ulonglong2* hp2 = (const ulonglong2*)(&hsm[buf][g * 36]);
            u64 ar = 0ULL, az = 0ULL, an = 0ULL;
#pragma unroll
            for (int q = 0; q < 8; q++) {
                ulonglong2 hv = hp2[q];
                ar = ffma2(wr[2 * q], hv.x, ar);
                ar = ffma2(wr[2 * q + 1], hv.y, ar);
                az = ffma2(wz[2 * q], hv.x, az);
                az = ffma2(wz[2 * q + 1], hv.y, az);
                an = ffma2(wn[2 * q], hv.x, an);
                an = ffma2(wn[2 * q + 1], hv.y, an);
            }
            float2 fr = unpack2(ar), fz = unpack2(az), fn = unpack2(an);
            float sr = fr.x + fr.y, sz = fz.x + fz.y, sn = fn.x + fn.y;
            sr += __shfl_xor_sync(0xffffffffu, sr, 1);
            sr += __shfl_xor_sync(0xffffffffu, sr, 2);
            sz += __shfl_xor_sync(0xffffffffu, sz, 1);
            sz += __shfl_xor_sync(0xffffffffu, sz, 2);
            sn += __shfl_xor_sync(0xffffffffu, sn, 1);
            sn += __shfl_xor_sync(0xffffffffu, sn, 2);
            float gr = __shfl_sync(0xffffffffu, gcur, laneBase + 0);
            float gz = __shfl_sync(0xffffffffu, gcur, laneBase + 1);
            float gn = __shfl_sync(0xffffffffu, gcur, laneBase + 2);
            float r  = sig_mufu(gr + sr + br);
            float zv = sig_mufu(gz + sz + bz);
            float n  = tanh_mufu(fmaf(r, sn + bn, gn));
            float hnew = fmaf(zv, hprev - n, n);
            hprev = hnew;
            if (g == 0) {
                hsm[buf ^ 1][hsl] = hnew;
                ll idx = obase + (ll)tt * 256;
                if (wbf) {
                    __nv_bfloat16 h16 = __float2bfloat16(hnew);
                    ohi[idx] = h16;
                    olo[idx] = __float2bfloat16(hnew - __bfloat162float(h16));
                } else {
                    outf[idx] = hnew;
                }
            }
            __syncthreads();
            buf ^= 1;
            tt += step;
        }
    }
}

// ---------------- pooling, parallelized ----------------
__global__ __launch_bounds__(256) void scores_k(
    const float* __restrict__ z1, const float* __restrict__ attn_w,
    const float* __restrict__ attn_b, float* __restrict__ sc)
{
    const int b = blockIdx.y;
    const int t = blockIdx.x * 8 + (threadIdx.x >> 5);
    const int lane = threadIdx.x & 31;
    const float* zr = z1 + ((ll)b * 1024 + t) * 256 + lane * 8;
    const float* ap = attn_w + lane * 8;
    float4 v0 = *(const float4*)zr;
    float4 v1 = *(const float4*)(zr + 4);
    float4 w0 = __ldg((const float4*)ap);
    float4 w1 = __ldg((const float4*)(ap + 4));
    float p = v0.x * w0.x;
    p = fmaf(v0.y, w0.y, p); p = fmaf(v0.z, w0.z, p); p = fmaf(v0.w, w0.w, p);
    p = fmaf(v1.x, w1.x, p); p = fmaf(v1.y, w1.y, p);
    p = fmaf(v1.z, w1.z, p); p = fmaf(v1.w, w1.w, p);
#pragma unroll
    for (int o = 16; o; o >>= 1) p += __shfl_down_sync(0xffffffffu, p, o);
    if (lane == 0) sc[b * 1024 + t] = p + __ldg(&attn_b[0]);
}

__global__ __launch_bounds__(256) void softmax_k(
    const float* __restrict__ sc, float* __restrict__ a)
{
    const int b = blockIdx.x;
    const int tid = threadIdx.x;
    const int lane = tid & 31;
    const int wrp = tid >> 5;
    __shared__ float red[34];

    float4 v = ((const float4*)(sc + b * 1024))[tid];
    float mx = fmaxf(fmaxf(v.x, v.y), fmaxf(v.z, v.w));
#pragma unroll
    for (int o = 16; o; o >>= 1) mx = fmaxf(mx, __shfl_xor_sync(0xffffffffu, mx, o));
    if (lane == 0) red[wrp] = mx;
    __syncthreads();
    if (tid == 0) {
        float m = red[0];
        for (int i = 1; i < 8; i++) m = fmaxf(m, red[i]);
        red[32] = m;
    }
    __syncthreads();
    mx = red[32];
    float e0 = __expf(v.x - mx), e1 = __expf(v.y - mx);
    float e2 = __expf(v.z - mx), e3 = __expf(v.w - mx);
    float s = (e0 + e1) + (e2 + e3);
#pragma unroll
    for (int o = 16; o; o >>= 1) s += __shfl_xor_sync(0xffffffffu, s, o);
    if (lane == 0) red[wrp] = s;
    __syncthreads();
    if (tid == 0) {
        float m = 0.0f;
        for (int i = 0; i < 8; i++) m += red[i];
        red[33] = __fdividef(1.0f, m);
    }
    __syncthreads();
    const float inv = red[33];
    float4 o4 = make_float4(e0 * inv, e1 * inv, e2 * inv, e3 * inv);
    ((float4*)(a + b * 1024))[tid] = o4;
}

__global__ __launch_bounds__(256) void part_k(
    const float* __restrict__ z1, const float* __restrict__ a,
    float* __restrict__ part)
{
    const int chunk = blockIdx.x;   // 0..15
    const int b = blockIdx.y;
    const int tid = threadIdx.x;
    __shared__ float asm_[64];
    if (tid < 64) asm_[tid] = a[b * 1024 + chunk * 64 + tid];
    __syncthreads();
    const float* zb = z1 + ((ll)b * 1024 + chunk * 64) * 256 + tid;
    float a0 = 0.0f, a1 = 0.0f, a2 = 0.0f, a3 = 0.0f;
#pragma unroll
    for (int t = 0; t < 64; t += 4) {
        a0 = fmaf(asm_[t + 0], zb[(t + 0) * 256], a0);
        a1 = fmaf(asm_[t + 1], zb[(t + 1) * 256], a1);
        a2 = fmaf(asm_[t + 2], zb[(t + 2) * 256], a2);
        a3 = fmaf(asm_[t + 3], zb[(t + 3) * 256], a3);
    }
    part[(b * 16 + chunk) * 256 + tid] = (a0 + a1) + (a2 + a3);
}

__global__ __launch_bounds__(256) void heads_k(
    const float* __restrict__ part,
    const float* __restrict__ motor_w, const float* __restrict__ motor_b,
    const float* __restrict__ state_w, const float* __restrict__ state_b,
    const int* __restrict__ motor_k, float* __restrict__ out)
{
    const int b = blockIdx.x;
    const int tid = threadIdx.x;
    const int lane = tid & 31;
    const int wrp = tid >> 5;
    __shared__ float pl[256];

    float s = 0.0f;
#pragma unroll
    for (int c = 0; c < 16; c++)
        s += part[(b * 16 + c) * 256 + tid];
    pl[tid] = s;
    __syncthreads();

    if (wrp < 7) {
        const float* wv;
        float bias2;
        int k = motor_k[b];
        if (wrp < 5) {
            wv = motor_w + wrp * 256;
            bias2 = motor_b[wrp];
        } else {
            int c = wrp - 5;
            wv = state_w + (k * 2 + c) * 256;
            bias2 = state_b[k * 2 + c];
        }
        float p = 0.0f;
#pragma unroll
        for (int q = 0; q < 8; q++)
            p = fmaf(pl[lane + 32 * q], wv[lane + 32 * q], p);
#pragma unroll
        for (int o = 16; o; o >>= 1) p += __shfl_down_sync(0xffffffffu, p, o);
        if (lane == 0) {
            if (wrp < 5) out[b * 5 + wrp] = p + bias2;
            else         out[320 + b * 2 + (wrp - 5)] = p + bias2;
        }
    }
}

// ---------------- launcher ----------------
extern "C" void kernel_launch(void* const* d_in, const int* in_sizes, int n_in,
                              void* d_out, int out_size)
{
    const float* x        = (const float*)d_in[0];
    const int*   motor_k  = (const int*)d_in[1];
    const float* wih_l0f  = (const float*)d_in[2];
    const float* whh_l0f  = (const float*)d_in[3];
    const float* bih_l0f  = (const float*)d_in[4];
    const float* bhh_l0f  = (const float*)d_in[5];
    const float* wih_l0b  = (const float*)d_in[6];
    const float* whh_l0b  = (const float*)d_in[7];
    const float* bih_l0b  = (const float*)d_in[8];
    const float* bhh_l0b  = (const float*)d_in[9];
    const float* wih_l1f  = (const float*)d_in[10];
    const float* whh_l1f  = (const float*)d_in[11];
    const float* bih_l1f  = (const float*)d_in[12];
    const float* bhh_l1f  = (const float*)d_in[13];
    const float* wih_l1b  = (const float*)d_in[14];
    const float* whh_l1b  = (const float*)d_in[15];
    const float* bih_l1b  = (const float*)d_in[16];
    const float* bhh_l1b  = (const float*)d_in[17];
    const float* attn_w   = (const float*)d_in[18];
    const float* attn_b   = (const float*)d_in[19];
    const float* motor_w  = (const float*)d_in[20];
    const float* motor_b  = (const float*)d_in[21];
    const float* state_w  = (const float*)d_in[22];
    const float* state_b  = (const float*)d_in[23];

    float *gif, *gib, *z1, *attn, *partp;
    __nv_bfloat16 *ahi, *alo, *whiF, *wloF, *whiB, *wloB;
    cudaGetSymbolAddress((void**)&gif, g_gi_f);
    cudaGetSymbolAddress((void**)&gib, g_gi_b);
    cudaGetSymbolAddress((void**)&z1, g_z1);
    cudaGetSymbolAddress((void**)&attn, g_attn);
    cudaGetSymbolAddress((void**)&partp, g_part);
    cudaGetSymbolAddress((void**)&ahi, g_ahi);
    cudaGetSymbolAddress((void**)&alo, g_alo);
    cudaGetSymbolAddress((void**)&whiF, g_whi_f);
    cudaGetSymbolAddress((void**)&wloF, g_wlo_f);
    cudaGetSymbolAddress((void**)&whiB, g_whi_b);
    cudaGetSymbolAddress((void**)&wloB, g_wlo_b);

    dim3 gg(3, 512, 2);

    // ---- layer 0 (K=64): x -> bf16, gemm, scan (scan emits bf16 hi/lo) ----
    split_bf16<<<4096, 256>>>(x, ahi, alo, 65536 * 64 / 4);
    split_bf16<<<24, 256>>>(wih_l0f, whiF, wloF, 384 * 64 / 4);
    split_bf16<<<24, 256>>>(wih_l0b, whiB, wloB, 384 * 64 / 4);
    mma_gemm<<<gg, 256>>>(ahi, alo, whiF, wloF, whiB, wloB,
                          bih_l0f, bih_l0b, gif, gib, 64);
    gru_scan<<<128, 512>>>(gif, gib, whh_l0f, bhh_l0f, whh_l0b, bhh_l0b,
                           (float*)0, ahi, alo, 1);

    // ---- layer 1 (K=256): gemm on scan's bf16 output, scan -> float z1 ----
    split_bf16<<<96, 256>>>(wih_l1f, whiF, wloF, 384 * 256 / 4);
    split_bf16<<<96, 256>>>(wih_l1b, whiB, wloB, 384 * 256 / 4);
    mma_gemm<<<gg, 256>>>(ahi, alo, whiF, wloF, whiB, wloB,
                          bih_l1f, bih_l1b, gif, gib, 256);
    gru_scan<<<128, 512>>>(gif, gib, whh_l1f, bhh_l1f, whh_l1b, bhh_l1b,
                           z1, (__nv_bfloat16*)0, (__nv_bfloat16*)0, 0);

    // ---- pooling + heads (parallelized) ----
    scores_k<<<dim3(128, 64), 256>>>(z1, attn_w, attn_b, attn);
    softmax_k<<<64, 256>>>(attn, attn);
    part_k<<<dim3(16, 64), 256>>>(z1, attn, partp);
    heads_k<<<64, 256>>>(partp, motor_w, motor_b, state_w, state_b,
                         motor_k, (float*)d_out);
}